// round 1
// baseline (speedup 1.0000x reference)
#include <cuda_runtime.h>
#include <cstdint>

#define N_NODES 100000
#define N_EDGES 3200000
#define D_IN 128
#define ATT 64
#define HEADS 4
#define NH (N_NODES * HEADS)
#define EH (N_EDGES * HEADS)

// ---------------- scratch (device globals; no allocation) ----------------
__device__ float g_q[(size_t)N_NODES * ATT];
__device__ float g_k[(size_t)N_NODES * ATT];
__device__ float g_sum[NH];
__device__ int   g_src[N_EDGES];
__device__ int   g_dst[N_EDGES];
__device__ int   g_is64;

// ---------------- edge dtype detection ----------------
// If edge tensor is int64 (little-endian, values in [0,1e5)), every odd 32-bit
// word of the first 2048 pairs is zero. If it's int32, those words are edge
// indices (~random in [0,1e5)) and almost surely not all zero.
__global__ void k_detect(const int* __restrict__ e32) {
    int any = 0;
    for (int i = threadIdx.x; i < 2048; i += blockDim.x)
        if (e32[2 * i + 1] != 0) any = 1;
    any = __syncthreads_or(any);
    if (threadIdx.x == 0) g_is64 = any ? 0 : 1;
}

// ---------------- prep: convert edges to int32 scratch, zero segment sums ----
__global__ void k_prep(const void* __restrict__ edge_raw) {
    const int stride = gridDim.x * blockDim.x;
    const int tid = blockIdx.x * blockDim.x + threadIdx.x;
    const int is64 = g_is64;
    if (is64) {
        const long long* e = (const long long*)edge_raw;
        for (int j = tid; j < N_EDGES; j += stride) {
            g_src[j] = (int)e[j];
            g_dst[j] = (int)e[N_EDGES + j];
        }
    } else {
        const int* e = (const int*)edge_raw;
        for (int j = tid; j < N_EDGES; j += stride) {
            g_src[j] = e[j];
            g_dst[j] = e[N_EDGES + j];
        }
    }
    for (int j = tid; j < NH; j += stride) g_sum[j] = 0.0f;
}

// ---------------- fused QKV projection ----------------
// One block: 128 rows x 192 cols (64 Q | 64 K | 64 V). 512 threads.
// Thread (rg = tid/32, lane = tid%32) computes 8 rows (4 f32x2 pairs) x 6 cols.
// Row pairs are accumulated with packed fma.rn.f32x2 (2 fp32 FMA / instr).
#define PROJ_THREADS 512
#define RPB 128           // rows per block
#define COLS 192
#define XS (RPB + 2)      // padded row stride for Xsm (even -> 8B-aligned pairs)

#define PROJ_SMEM_BYTES ((D_IN * COLS + COLS + D_IN * XS) * 4)

__global__ void __launch_bounds__(PROJ_THREADS, 1)
k_proj(const float* __restrict__ x,
       const float* __restrict__ WQ, const float* __restrict__ bQ,
       const float* __restrict__ WK, const float* __restrict__ bK,
       const float* __restrict__ WV, const float* __restrict__ bV,
       float* __restrict__ out_v) {
    extern __shared__ float smem[];
    float* Wsm = smem;                    // [128][192]
    float* bsm = Wsm + D_IN * COLS;       // [192]
    float* Xsm = bsm + COLS;              // [128][XS] (x transposed: d major, row minor)

    const int tid = threadIdx.x;

    // Stage fused weight matrix [d][m]: m<64 -> WQ, <128 -> WK, else WV
    for (int i = tid; i < D_IN * COLS; i += PROJ_THREADS) {
        int d = i / COLS, m = i % COLS;
        float w;
        if (m < 64)       w = WQ[d * 64 + m];
        else if (m < 128) w = WK[d * 64 + (m - 64)];
        else              w = WV[d * 64 + (m - 128)];
        Wsm[i] = w;
    }
    for (int i = tid; i < COLS; i += PROJ_THREADS)
        bsm[i] = (i < 64) ? bQ[i] : (i < 128 ? bK[i - 64] : bV[i - 128]);

    const int row0 = blockIdx.x * RPB;
    // Stage x tile transposed: coalesced gmem read, padded smem write
    for (int i = tid; i < RPB * D_IN; i += PROJ_THREADS) {
        int r = i / D_IN, d = i % D_IN;
        int row = row0 + r;
        Xsm[d * XS + r] = (row < N_NODES) ? x[(size_t)row * D_IN + d] : 0.0f;
    }
    __syncthreads();

    const int lane = tid & 31;
    const int rbase = (tid >> 5) * 8;     // 8 rows per thread

    unsigned long long acc[4][6];
#pragma unroll
    for (int p = 0; p < 4; p++)
#pragma unroll
        for (int j = 0; j < 6; j++) acc[p][j] = 0ull;

#pragma unroll 4
    for (int d = 0; d < D_IN; d++) {
        const float* xr = &Xsm[d * XS + rbase];
        unsigned long long x01 = *reinterpret_cast<const unsigned long long*>(xr + 0);
        unsigned long long x23 = *reinterpret_cast<const unsigned long long*>(xr + 2);
        unsigned long long x45 = *reinterpret_cast<const unsigned long long*>(xr + 4);
        unsigned long long x67 = *reinterpret_cast<const unsigned long long*>(xr + 6);
        const float* wr = &Wsm[d * COLS + lane];
#pragma unroll
        for (int j = 0; j < 6; j++) {
            float w = wr[j * 32];
            unsigned long long ww;
            asm("mov.b64 %0, {%1, %1};" : "=l"(ww) : "r"(__float_as_uint(w)));
            asm("fma.rn.f32x2 %0, %1, %2, %0;" : "+l"(acc[0][j]) : "l"(x01), "l"(ww));
            asm("fma.rn.f32x2 %0, %1, %2, %0;" : "+l"(acc[1][j]) : "l"(x23), "l"(ww));
            asm("fma.rn.f32x2 %0, %1, %2, %0;" : "+l"(acc[2][j]) : "l"(x45), "l"(ww));
            asm("fma.rn.f32x2 %0, %1, %2, %0;" : "+l"(acc[3][j]) : "l"(x67), "l"(ww));
        }
    }

    // Epilogue: add bias, scatter to q/k scratch and transposed v output
#pragma unroll
    for (int p = 0; p < 4; p++) {
#pragma unroll
        for (int j = 0; j < 6; j++) {
            unsigned long long a = acc[p][j];
            float v0 = __uint_as_float((unsigned)(a & 0xFFFFFFFFull));
            float v1 = __uint_as_float((unsigned)(a >> 32));
            int m = lane + j * 32;
            float b = bsm[m];
            v0 += b; v1 += b;
            int r = row0 + rbase + p * 2;
#pragma unroll
            for (int s = 0; s < 2; s++) {
                int row = r + s;
                float val = s ? v1 : v0;
                if (row < N_NODES) {
                    if (m < 64) {
                        g_q[(size_t)row * 64 + m] = val;
                    } else if (m < 128) {
                        g_k[(size_t)row * 64 + (m - 64)] = val;
                    } else {
                        int c = m - 128;
                        int h = c >> 4, dd = c & 15;
                        // v_out layout [N, d_k, heads]
                        out_v[(size_t)row * 64 + dd * 4 + h] = val;
                    }
                }
            }
        }
    }
}

// ---------------- edge pass 1: prods, exp, segment sums ----------------
// 4 threads per edge (one per head). prods = dot16(q[src,h], k[dst,h]) / 4.
// Max-shift skipped: |prods| << 1 so exp() is safe and the shift cancels exactly.
__global__ void k_edge1(float* __restrict__ out_att, float* __restrict__ out_prods) {
    int i = blockIdx.x * blockDim.x + threadIdx.x;
    if (i >= EH) return;
    int e = i >> 2, h = i & 3;
    int src = g_src[e];
    int dst = g_dst[e];
    const float4* qp = reinterpret_cast<const float4*>(&g_q[(size_t)src * 64 + h * 16]);
    const float4* kp = reinterpret_cast<const float4*>(&g_k[(size_t)dst * 64 + h * 16]);
    float dot = 0.0f;
#pragma unroll
    for (int t = 0; t < 4; t++) {
        float4 a = qp[t];
        float4 b = kp[t];
        dot += a.x * b.x + a.y * b.y + a.z * b.z + a.w * b.w;
    }
    float p = dot * 0.25f;                 // 1/sqrt(16)
    out_prods[i] = p;
    float ex = __expf(p);
    out_att[i] = ex;                       // staged; normalized in k_edge2
    atomicAdd(&g_sum[src * 4 + h], ex);
}

// ---------------- edge pass 2: normalize ----------------
__global__ void k_edge2(float* __restrict__ out_att) {
    int i = blockIdx.x * blockDim.x + threadIdx.x;
    if (i >= EH) return;
    int e = i >> 2, h = i & 3;
    int src = g_src[e];
    out_att[i] = out_att[i] / (g_sum[src * 4 + h] + 1e-16f);
}

// ---------------- launch ----------------
extern "C" void kernel_launch(void* const* d_in, const int* in_sizes, int n_in,
                              void* d_out, int out_size) {
    const float* x  = (const float*)d_in[0];
    const void*  edge = d_in[1];
    const float* WQ = (const float*)d_in[2];
    const float* bQ = (const float*)d_in[3];
    const float* WK = (const float*)d_in[4];
    const float* bK = (const float*)d_in[5];
    const float* WV = (const float*)d_in[6];
    const float* bV = (const float*)d_in[7];

    float* out       = (float*)d_out;
    float* out_att   = out;                                   // [E, 4]
    float* out_v     = out + (size_t)EH;                      // [N, 16, 4]
    float* out_prods = out_v + (size_t)N_NODES * ATT;         // [E, 4]

    cudaFuncSetAttribute(k_proj, cudaFuncAttributeMaxDynamicSharedMemorySize,
                         PROJ_SMEM_BYTES);

    k_detect<<<1, 256>>>((const int*)edge);
    k_prep<<<4096, 256>>>(edge);

    int proj_blocks = (N_NODES + RPB - 1) / RPB;              // 782
    k_proj<<<proj_blocks, PROJ_THREADS, PROJ_SMEM_BYTES>>>(
        x, WQ, bQ, WK, bK, WV, bV, out_v);

    int nt = EH;
    k_edge1<<<(nt + 255) / 256, 256>>>(out_att, out_prods);
    k_edge2<<<(nt + 255) / 256, 256>>>(out_att);
}

// round 2
// speedup vs baseline: 1.3142x; 1.3142x over previous
#include <cuda_runtime.h>
#include <cuda_fp16.h>
#include <cstdint>

#define N_NODES 100000
#define N_EDGES 3200000
#define D_IN 128
#define ATT 64
#define HEADS 4
#define NH (N_NODES * HEADS)
#define EH (N_EDGES * HEADS)

// ---------------- scratch (device globals; no allocation) ----------------
__device__ __align__(128) __half g_qh[(size_t)N_NODES * ATT];  // fp16 q rows, 128B each
__device__ __align__(128) __half g_kh[(size_t)N_NODES * ATT];  // fp16 k rows
__device__ __align__(16)  float  g_sum[NH];
__device__ int g_src[N_EDGES];
__device__ int g_dst[N_EDGES];
__device__ int g_is64;

// ---------------- edge dtype detection ----------------
// int64 edges (values < 1e5) have all-zero high words; int32 edge data would
// have ~random values in those slots.
__global__ void k_detect(const int* __restrict__ e32) {
    int any = 0;
    for (int i = threadIdx.x; i < 2048; i += blockDim.x)
        if (e32[2 * i + 1] != 0) any = 1;
    any = __syncthreads_or(any);
    if (threadIdx.x == 0) g_is64 = any ? 0 : 1;
}

// ---------------- prep: edges -> int32 scratch, zero segment sums ----------
__global__ void k_prep(const void* __restrict__ edge_raw) {
    const int stride = gridDim.x * blockDim.x;
    const int tid = blockIdx.x * blockDim.x + threadIdx.x;
    const int is64 = g_is64;
    if (is64) {
        const long long* e = (const long long*)edge_raw;
        for (int j = tid; j < N_EDGES; j += stride) {
            g_src[j] = (int)e[j];
            g_dst[j] = (int)e[N_EDGES + j];
        }
    } else {
        const int* e = (const int*)edge_raw;
        for (int j = tid; j < N_EDGES; j += stride) {
            g_src[j] = e[j];
            g_dst[j] = e[N_EDGES + j];
        }
    }
    for (int j = tid; j < NH; j += stride) g_sum[j] = 0.0f;
}

// ---------------- fused QKV projection ----------------
// One block: 128 rows x 192 cols (64 Q | 64 K | 64 V). 512 threads.
// Thread computes 8 rows (4 f32x2 pairs) x 6 cols via packed fma.rn.f32x2.
#define PROJ_THREADS 512
#define RPB 128
#define COLS 192
#define XS (RPB + 2)

#define PROJ_SMEM_BYTES ((D_IN * COLS + COLS + D_IN * XS) * 4)

__global__ void __launch_bounds__(PROJ_THREADS, 1)
k_proj(const float* __restrict__ x,
       const float* __restrict__ WQ, const float* __restrict__ bQ,
       const float* __restrict__ WK, const float* __restrict__ bK,
       const float* __restrict__ WV, const float* __restrict__ bV,
       float* __restrict__ out_v) {
    extern __shared__ float smem[];
    float* Wsm = smem;                    // [128][192]
    float* bsm = Wsm + D_IN * COLS;       // [192]
    float* Xsm = bsm + COLS;              // [128][XS] (x transposed)

    const int tid = threadIdx.x;

    for (int i = tid; i < D_IN * COLS; i += PROJ_THREADS) {
        int d = i / COLS, m = i % COLS;
        float w;
        if (m < 64)       w = WQ[d * 64 + m];
        else if (m < 128) w = WK[d * 64 + (m - 64)];
        else              w = WV[d * 64 + (m - 128)];
        Wsm[i] = w;
    }
    for (int i = tid; i < COLS; i += PROJ_THREADS)
        bsm[i] = (i < 64) ? bQ[i] : (i < 128 ? bK[i - 64] : bV[i - 128]);

    const int row0 = blockIdx.x * RPB;
    for (int i = tid; i < RPB * D_IN; i += PROJ_THREADS) {
        int r = i / D_IN, d = i % D_IN;
        int row = row0 + r;
        Xsm[d * XS + r] = (row < N_NODES) ? x[(size_t)row * D_IN + d] : 0.0f;
    }
    __syncthreads();

    const int lane = tid & 31;
    const int rbase = (tid >> 5) * 8;

    unsigned long long acc[4][6];
#pragma unroll
    for (int p = 0; p < 4; p++)
#pragma unroll
        for (int j = 0; j < 6; j++) acc[p][j] = 0ull;

#pragma unroll 4
    for (int d = 0; d < D_IN; d++) {
        const float* xr = &Xsm[d * XS + rbase];
        unsigned long long x01 = *reinterpret_cast<const unsigned long long*>(xr + 0);
        unsigned long long x23 = *reinterpret_cast<const unsigned long long*>(xr + 2);
        unsigned long long x45 = *reinterpret_cast<const unsigned long long*>(xr + 4);
        unsigned long long x67 = *reinterpret_cast<const unsigned long long*>(xr + 6);
        const float* wr = &Wsm[d * COLS + lane];
#pragma unroll
        for (int j = 0; j < 6; j++) {
            float w = wr[j * 32];
            unsigned long long ww;
            asm("mov.b64 %0, {%1, %1};" : "=l"(ww) : "r"(__float_as_uint(w)));
            asm("fma.rn.f32x2 %0, %1, %2, %0;" : "+l"(acc[0][j]) : "l"(x01), "l"(ww));
            asm("fma.rn.f32x2 %0, %1, %2, %0;" : "+l"(acc[1][j]) : "l"(x23), "l"(ww));
            asm("fma.rn.f32x2 %0, %1, %2, %0;" : "+l"(acc[2][j]) : "l"(x45), "l"(ww));
            asm("fma.rn.f32x2 %0, %1, %2, %0;" : "+l"(acc[3][j]) : "l"(x67), "l"(ww));
        }
    }

    // Epilogue: bias, then q/k -> fp16 scratch, v -> transposed fp32 output
#pragma unroll
    for (int p = 0; p < 4; p++) {
#pragma unroll
        for (int j = 0; j < 6; j++) {
            unsigned long long a = acc[p][j];
            float v0 = __uint_as_float((unsigned)(a & 0xFFFFFFFFull));
            float v1 = __uint_as_float((unsigned)(a >> 32));
            int m = lane + j * 32;
            float b = bsm[m];
            v0 += b; v1 += b;
            int r = row0 + rbase + p * 2;
#pragma unroll
            for (int s = 0; s < 2; s++) {
                int row = r + s;
                float val = s ? v1 : v0;
                if (row < N_NODES) {
                    if (m < 64) {
                        g_qh[(size_t)row * 64 + m] = __float2half_rn(val);
                    } else if (m < 128) {
                        g_kh[(size_t)row * 64 + (m - 64)] = __float2half_rn(val);
                    } else {
                        int c = m - 128;
                        int h = c >> 4, dd = c & 15;
                        out_v[(size_t)row * 64 + dd * 4 + h] = val;  // [N, d_k, h]
                    }
                }
            }
        }
    }
}

// ---------------- edge pass 1: prods, exp, segment sums ----------------
// 8 lanes per edge: each lane loads 16B (8 fp16) of the 128B q row and k row,
// so one warp-level LDG.128 covers 4 full rows (4 L1 wavefronts vs 32 before).
// Lane sub covers halves [8*sub, 8*sub+8) = half of head (sub>>1); pair-reduce
// via shfl_xor(1). Max-shift skipped (|prods| << 1, cancels exactly).
__global__ void k_edge1(float* __restrict__ out_att, float* __restrict__ out_prods) {
    int t = blockIdx.x * blockDim.x + threadIdx.x;
    int e = t >> 3;
    if (e >= N_EDGES) return;
    int sub = t & 7;

    int src = g_src[e];
    int dst = g_dst[e];
    const uint4* qr = reinterpret_cast<const uint4*>(g_qh + (size_t)src * 64);
    const uint4* kr = reinterpret_cast<const uint4*>(g_kh + (size_t)dst * 64);
    uint4 qv = qr[sub];
    uint4 kv = kr[sub];
    const __half2* qh = reinterpret_cast<const __half2*>(&qv);
    const __half2* kh = reinterpret_cast<const __half2*>(&kv);

    float dot = 0.0f;
#pragma unroll
    for (int i = 0; i < 4; i++) {
        float2 a = __half22float2(qh[i]);
        float2 b = __half22float2(kh[i]);
        dot = fmaf(a.x, b.x, dot);
        dot = fmaf(a.y, b.y, dot);
    }
    dot += __shfl_xor_sync(0xffffffffu, dot, 1);

    if ((sub & 1) == 0) {
        int h = sub >> 1;
        int i = e * 4 + h;
        float p = dot * 0.25f;            // 1/sqrt(16)
        out_prods[i] = p;
        float ex = __expf(p);
        out_att[i] = ex;                  // staged; normalized in k_edge2
        atomicAdd(&g_sum[src * 4 + h], ex);
    }
}

// ---------------- edge pass 2: normalize (thread per edge, float4) --------
__global__ void k_edge2(float* __restrict__ out_att) {
    int e = blockIdx.x * blockDim.x + threadIdx.x;
    if (e >= N_EDGES) return;
    int src = g_src[e];
    float4 ex = reinterpret_cast<float4*>(out_att)[e];
    float4 s  = reinterpret_cast<const float4*>(g_sum)[src];
    ex.x = __fdividef(ex.x, s.x + 1e-16f);
    ex.y = __fdividef(ex.y, s.y + 1e-16f);
    ex.z = __fdividef(ex.z, s.z + 1e-16f);
    ex.w = __fdividef(ex.w, s.w + 1e-16f);
    reinterpret_cast<float4*>(out_att)[e] = ex;
}

// ---------------- launch ----------------
extern "C" void kernel_launch(void* const* d_in, const int* in_sizes, int n_in,
                              void* d_out, int out_size) {
    const float* x  = (const float*)d_in[0];
    const void*  edge = d_in[1];
    const float* WQ = (const float*)d_in[2];
    const float* bQ = (const float*)d_in[3];
    const float* WK = (const float*)d_in[4];
    const float* bK = (const float*)d_in[5];
    const float* WV = (const float*)d_in[6];
    const float* bV = (const float*)d_in[7];

    float* out       = (float*)d_out;
    float* out_att   = out;                                   // [E, 4]
    float* out_v     = out + (size_t)EH;                      // [N, 16, 4]
    float* out_prods = out_v + (size_t)N_NODES * ATT;         // [E, 4]

    cudaFuncSetAttribute(k_proj, cudaFuncAttributeMaxDynamicSharedMemorySize,
                         PROJ_SMEM_BYTES);

    k_detect<<<1, 256>>>((const int*)edge);
    k_prep<<<4096, 256>>>(edge);

    int proj_blocks = (N_NODES + RPB - 1) / RPB;              // 782
    k_proj<<<proj_blocks, PROJ_THREADS, PROJ_SMEM_BYTES>>>(
        x, WQ, bQ, WK, bK, WV, bV, out_v);

    int nt1 = N_EDGES * 8;
    k_edge1<<<(nt1 + 255) / 256, 256>>>(out_att, out_prods);
    k_edge2<<<(N_EDGES + 255) / 256, 256>>>(out_att);
}

// round 3
// speedup vs baseline: 1.8990x; 1.4450x over previous
#include <cuda_runtime.h>
#include <cuda_fp16.h>
#include <cstdint>

#define N_NODES 100000
#define N_EDGES 3200000
#define D_IN 128
#define ATT 64
#define HEADS 4
#define NH (N_NODES * HEADS)
#define EH (N_EDGES * HEADS)
#define COLS 192

// ---------------- scratch (device globals; no allocation) ----------------
__device__ __align__(128) __half g_qh[(size_t)N_NODES * ATT];   // fp16 q rows (128B/row)
__device__ __align__(128) __half g_kh[(size_t)N_NODES * ATT];   // fp16 k rows
__device__ __align__(16)  float  g_sum[NH];
__device__ int g_src[N_EDGES];
__device__ int g_dst[N_EDGES];
__device__ int g_is64;
// fused transposed weights, fp16 hi/lo split: Wt[m][d], m in [0,192), d in [0,128)
__device__ __align__(16) __half g_wth[COLS * D_IN];
__device__ __align__(16) __half g_wtl[COLS * D_IN];

// ---------------- edge dtype detection ----------------
__global__ void k_detect(const int* __restrict__ e32) {
    int any = 0;
    for (int i = threadIdx.x; i < 2048; i += blockDim.x)
        if (e32[2 * i + 1] != 0) any = 1;
    any = __syncthreads_or(any);
    if (threadIdx.x == 0) g_is64 = any ? 0 : 1;
}

// ---------------- prep: edges -> int32 scratch, zero segment sums ----------
__global__ void k_prep(const void* __restrict__ edge_raw) {
    const int stride = gridDim.x * blockDim.x;
    const int tid = blockIdx.x * blockDim.x + threadIdx.x;
    if (g_is64) {
        const long long* e = (const long long*)edge_raw;
        for (int j = tid; j < N_EDGES; j += stride) {
            g_src[j] = (int)e[j];
            g_dst[j] = (int)e[N_EDGES + j];
        }
    } else {
        const int* e = (const int*)edge_raw;
        for (int j = tid; j < N_EDGES; j += stride) {
            g_src[j] = e[j];
            g_dst[j] = e[N_EDGES + j];
        }
    }
    for (int j = tid; j < NH; j += stride) g_sum[j] = 0.0f;
}

// ---------------- W transpose + fp16 hi/lo split ----------------
__global__ void k_wconv(const float* __restrict__ WQ, const float* __restrict__ WK,
                        const float* __restrict__ WV) {
    int i = blockIdx.x * blockDim.x + threadIdx.x;   // over 192*128
    if (i >= COLS * D_IN) return;
    int m = i >> 7, d = i & 127;
    float w;
    if (m < 64)       w = WQ[d * 64 + m];
    else if (m < 128) w = WK[d * 64 + (m - 64)];
    else              w = WV[d * 64 + (m - 128)];
    __half hi = __float2half_rn(w);
    g_wth[i] = hi;
    g_wtl[i] = __float2half_rn(w - __half2float(hi));
}

// ---------------- HMMA split-fp16 QKV projection ----------------
// Block: 128 rows x 192 cols, K=128. 256 threads = 8 warps (2 M x 4 N).
// Warp tile 64x48 = 4x6 m16n8k16 mma tiles. 3-term split: AhBh + AlBh + AhBl.
#define PROJ_THREADS 256
#define RPB 128
#define KS 136                     // smem row stride in halfs (bank-stride 4 -> conflict-free)

// smem layout (halfs unless noted)
#define SM_XH 0
#define SM_XL (SM_XH + RPB * KS)              // 17408
#define SM_WH (SM_XL + RPB * KS)              // 34816
#define SM_WL (SM_WH + COLS * KS)             // 60928
#define SM_END (SM_WL + COLS * KS)            // 87040 halfs
#define PROJ_SMEM_BYTES (SM_END * 2 + COLS * 4)   // + fp32 bias

#define MMA3(acc, ra, rb)                                                        \
    asm volatile("mma.sync.aligned.m16n8k16.row.col.f32.f16.f16.f32 "            \
        "{%0,%1,%2,%3}, {%4,%5,%6,%7}, {%8,%9}, {%0,%1,%2,%3};"                  \
        : "+f"(acc[0]), "+f"(acc[1]), "+f"(acc[2]), "+f"(acc[3])                 \
        : "r"(ra[0]), "r"(ra[1]), "r"(ra[2]), "r"(ra[3]), "r"(rb[0]), "r"(rb[1]))

__global__ void __launch_bounds__(PROJ_THREADS, 1)
k_proj(const float* __restrict__ x,
       const float* __restrict__ bQ, const float* __restrict__ bK,
       const float* __restrict__ bV, float* __restrict__ out_v) {
    extern __shared__ __half sm[];
    float* bsm = (float*)(sm + SM_END);

    const int tid = threadIdx.x;
    const int row0 = blockIdx.x * RPB;

    // ---- stage W hi/lo (global fp16 -> padded smem), uint4 chunks of 8 halfs
    {
        const uint4* wh_g = (const uint4*)g_wth;
        const uint4* wl_g = (const uint4*)g_wtl;
        for (int i = tid; i < COLS * D_IN / 8; i += PROJ_THREADS) {
            int m = i >> 4, d8 = (i & 15) * 8;
            *(uint4*)(sm + SM_WH + m * KS + d8) = wh_g[i];
            *(uint4*)(sm + SM_WL + m * KS + d8) = wl_g[i];
        }
    }
    // ---- stage x -> fp16 hi/lo (8 floats per chunk)
    for (int i = tid; i < RPB * D_IN / 8; i += PROJ_THREADS) {
        int r = i >> 4, d8 = (i & 15) * 8;
        int row = row0 + r;
        float f[8];
        if (row < N_NODES) {
            const float4* xp = (const float4*)(x + (size_t)row * D_IN + d8);
            float4 v0 = xp[0], v1 = xp[1];
            f[0]=v0.x; f[1]=v0.y; f[2]=v0.z; f[3]=v0.w;
            f[4]=v1.x; f[5]=v1.y; f[6]=v1.z; f[7]=v1.w;
        } else {
#pragma unroll
            for (int t = 0; t < 8; t++) f[t] = 0.0f;
        }
        __half hi[8], lo[8];
#pragma unroll
        for (int t = 0; t < 8; t++) {
            hi[t] = __float2half_rn(f[t]);
            lo[t] = __float2half_rn(f[t] - __half2float(hi[t]));
        }
        *(uint4*)(sm + SM_XH + r * KS + d8) = *(const uint4*)hi;
        *(uint4*)(sm + SM_XL + r * KS + d8) = *(const uint4*)lo;
    }
    for (int i = tid; i < COLS; i += PROJ_THREADS)
        bsm[i] = (i < 64) ? bQ[i] : (i < 128 ? bK[i - 64] : bV[i - 128]);
    __syncthreads();

    const int lane = tid & 31;
    const int wid  = tid >> 5;
    const int wm   = wid >> 2;        // 0..1
    const int wn   = wid & 3;         // 0..3
    const int grp  = lane >> 2;       // 0..7
    const int tig  = lane & 3;        // 0..3

    float acc[4][6][4];
#pragma unroll
    for (int mi = 0; mi < 4; mi++)
#pragma unroll
        for (int ni = 0; ni < 6; ni++)
#pragma unroll
            for (int t = 0; t < 4; t++) acc[mi][ni][t] = 0.0f;

    // per-thread base offsets (halfs)
    int a_base = (wm * 64 + grp) * KS + tig * 2;          // + mi*16*KS
    int b_base = (wn * 48 + grp) * KS + tig * 2;          // + ni*8*KS

#pragma unroll
    for (int k0 = 0; k0 < 8; k0++) {
        const int kc = k0 * 16;
        uint32_t bh[6][2], bl[6][2];
#pragma unroll
        for (int ni = 0; ni < 6; ni++) {
            int o = b_base + ni * 8 * KS + kc;
            bh[ni][0] = *(const uint32_t*)(sm + SM_WH + o);
            bh[ni][1] = *(const uint32_t*)(sm + SM_WH + o + 8);
            bl[ni][0] = *(const uint32_t*)(sm + SM_WL + o);
            bl[ni][1] = *(const uint32_t*)(sm + SM_WL + o + 8);
        }
        uint32_t ah[4][4], al[4][4];
#pragma unroll
        for (int mi = 0; mi < 4; mi++) {
            int o = a_base + mi * 16 * KS + kc;
            ah[mi][0] = *(const uint32_t*)(sm + SM_XH + o);
            ah[mi][1] = *(const uint32_t*)(sm + SM_XH + o + 8 * KS);
            ah[mi][2] = *(const uint32_t*)(sm + SM_XH + o + 8);
            ah[mi][3] = *(const uint32_t*)(sm + SM_XH + o + 8 * KS + 8);
            al[mi][0] = *(const uint32_t*)(sm + SM_XL + o);
            al[mi][1] = *(const uint32_t*)(sm + SM_XL + o + 8 * KS);
            al[mi][2] = *(const uint32_t*)(sm + SM_XL + o + 8);
            al[mi][3] = *(const uint32_t*)(sm + SM_XL + o + 8 * KS + 8);
        }
#pragma unroll
        for (int mi = 0; mi < 4; mi++)
#pragma unroll
            for (int ni = 0; ni < 6; ni++) {
                MMA3(acc[mi][ni], ah[mi], bh[ni]);
                MMA3(acc[mi][ni], al[mi], bh[ni]);
                MMA3(acc[mi][ni], ah[mi], bl[ni]);
            }
    }

    // ---- epilogue: bias + scatter (q/k fp16 scratch, v transposed fp32 out)
#pragma unroll
    for (int mi = 0; mi < 4; mi++) {
#pragma unroll
        for (int ni = 0; ni < 6; ni++) {
            int c = wn * 48 + ni * 8 + tig * 2;          // even; tile region warp-uniform
            float b0 = bsm[c], b1 = bsm[c + 1];
#pragma unroll
            for (int half = 0; half < 2; half++) {
                int r = row0 + wm * 64 + mi * 16 + grp + half * 8;
                if (r >= N_NODES) continue;
                float v0 = acc[mi][ni][half * 2 + 0] + b0;
                float v1 = acc[mi][ni][half * 2 + 1] + b1;
                if (c < 64) {
                    __half2 hv = __floats2half2_rn(v0, v1);
                    *(__half2*)(g_qh + r * 64 + c) = hv;
                } else if (c < 128) {
                    __half2 hv = __floats2half2_rn(v0, v1);
                    *(__half2*)(g_kh + r * 64 + (c - 64)) = hv;
                } else {
                    int cc = c - 128;
                    int h = cc >> 4, dd = cc & 15;
                    out_v[(size_t)r * 64 + dd * 4 + h] = v0;
                    out_v[(size_t)r * 64 + (dd + 1) * 4 + h] = v1;
                }
            }
        }
    }
}

// ---------------- edge pass 1: prods, exp, segment sums ----------------
// 8 lanes/edge; lane sub loads 16B of each 128B row; pair-reduce via shfl.
__global__ void k_edge1(float* __restrict__ out_att, float* __restrict__ out_prods) {
    int t = blockIdx.x * blockDim.x + threadIdx.x;
    int e = t >> 3;
    if (e >= N_EDGES) return;
    int sub = t & 7;

    int src = g_src[e];
    int dst = g_dst[e];
    uint4 qv = *(const uint4*)(g_qh + src * 64 + sub * 8);   // 32-bit indexing
    uint4 kv = *(const uint4*)(g_kh + dst * 64 + sub * 8);
    const __half2* qh = reinterpret_cast<const __half2*>(&qv);
    const __half2* kh = reinterpret_cast<const __half2*>(&kv);

    float dot = 0.0f;
#pragma unroll
    for (int i = 0; i < 4; i++) {
        float2 a = __half22float2(qh[i]);
        float2 b = __half22float2(kh[i]);
        dot = fmaf(a.x, b.x, dot);
        dot = fmaf(a.y, b.y, dot);
    }
    dot += __shfl_xor_sync(0xffffffffu, dot, 1);

    if ((sub & 1) == 0) {
        int h = sub >> 1;
        int i = e * 4 + h;
        float p = dot * 0.25f;             // 1/sqrt(16)
        out_prods[i] = p;
        float ex = __expf(p);
        out_att[i] = ex;                   // staged; normalized in k_edge2
        atomicAdd(&g_sum[src * 4 + h], ex);
    }
}

// ---------------- edge pass 2: normalize ----------------
__global__ void k_edge2(float* __restrict__ out_att) {
    int e = blockIdx.x * blockDim.x + threadIdx.x;
    if (e >= N_EDGES) return;
    int src = g_src[e];
    float4 ex = reinterpret_cast<float4*>(out_att)[e];
    float4 s  = reinterpret_cast<const float4*>(g_sum)[src];
    ex.x = __fdividef(ex.x, s.x + 1e-16f);
    ex.y = __fdividef(ex.y, s.y + 1e-16f);
    ex.z = __fdividef(ex.z, s.z + 1e-16f);
    ex.w = __fdividef(ex.w, s.w + 1e-16f);
    reinterpret_cast<float4*>(out_att)[e] = ex;
}

// ---------------- launch ----------------
extern "C" void kernel_launch(void* const* d_in, const int* in_sizes, int n_in,
                              void* d_out, int out_size) {
    const float* x  = (const float*)d_in[0];
    const void*  edge = d_in[1];
    const float* WQ = (const float*)d_in[2];
    const float* bQ = (const float*)d_in[3];
    const float* WK = (const float*)d_in[4];
    const float* bK = (const float*)d_in[5];
    const float* WV = (const float*)d_in[6];
    const float* bV = (const float*)d_in[7];

    float* out       = (float*)d_out;
    float* out_att   = out;                                   // [E, 4]
    float* out_v     = out + (size_t)EH;                      // [N, 16, 4]
    float* out_prods = out_v + (size_t)N_NODES * ATT;         // [E, 4]

    cudaFuncSetAttribute(k_proj, cudaFuncAttributeMaxDynamicSharedMemorySize,
                         PROJ_SMEM_BYTES);

    k_detect<<<1, 256>>>((const int*)edge);
    k_prep<<<4096, 256>>>(edge);
    k_wconv<<<(COLS * D_IN + 255) / 256, 256>>>(WQ, WK, WV);

    int proj_blocks = (N_NODES + RPB - 1) / RPB;              // 782
    k_proj<<<proj_blocks, PROJ_THREADS, PROJ_SMEM_BYTES>>>(x, bQ, bK, bV, out_v);

    int nt1 = N_EDGES * 8;
    k_edge1<<<(nt1 + 255) / 256, 256>>>(out_att, out_prods);
    k_edge2<<<(N_EDGES + 255) / 256, 256>>>(out_att);
}

// round 4
// speedup vs baseline: 2.1581x; 1.1364x over previous
#include <cuda_runtime.h>
#include <cuda_fp16.h>
#include <cstdint>

#define N_NODES 100000
#define N_EDGES 3200000
#define D_IN 128
#define ATT 64
#define HEADS 4
#define NH (N_NODES * HEADS)
#define EH (N_EDGES * HEADS)
#define COLS 192

// ---------------- scratch (device globals; no allocation) ----------------
__device__ __align__(128) __half g_qh[(size_t)N_NODES * ATT];   // fp16 q rows (128B/row)
__device__ __align__(128) __half g_kh[(size_t)N_NODES * ATT];   // fp16 k rows
__device__ __align__(16)  float  g_sum[NH];
__device__ int g_is64;
// fused transposed weights, fp16 hi/lo split: Wt[m][d], m in [0,192), d in [0,128)
__device__ __align__(16) __half g_wth[COLS * D_IN];
__device__ __align__(16) __half g_wtl[COLS * D_IN];

// ---------------- edge dtype detection ----------------
__global__ void k_detect(const int* __restrict__ e32) {
    int any = 0;
    for (int i = threadIdx.x; i < 2048; i += blockDim.x)
        if (e32[2 * i + 1] != 0) any = 1;
    any = __syncthreads_or(any);
    if (threadIdx.x == 0) g_is64 = any ? 0 : 1;
}

// ---------------- zero segment sums ----------------
__global__ void k_zero() {
    int j = blockIdx.x * blockDim.x + threadIdx.x;
    if (j < NH) g_sum[j] = 0.0f;
}

// ---------------- W transpose + fp16 hi/lo split ----------------
__global__ void k_wconv(const float* __restrict__ WQ, const float* __restrict__ WK,
                        const float* __restrict__ WV) {
    int i = blockIdx.x * blockDim.x + threadIdx.x;   // over 192*128
    if (i >= COLS * D_IN) return;
    int m = i >> 7, d = i & 127;
    float w;
    if (m < 64)       w = WQ[d * 64 + m];
    else if (m < 128) w = WK[d * 64 + (m - 64)];
    else              w = WV[d * 64 + (m - 128)];
    __half hi = __float2half_rn(w);
    g_wth[i] = hi;
    g_wtl[i] = __float2half_rn(w - __half2float(hi));
}

// ---------------- HMMA 2-term split QKV projection ----------------
// Block: 128 rows x 96 cols (half of QKV), K=128. grid=(782,2).
// 256 threads = 8 warps (2M x 4N), warp tile 64x24 = 4x3 m16n8k16 tiles.
// D = Ah*(Bh + Bl): x quantized to fp16 (hi), W kept at near-fp32 via hi/lo.
#define PROJ_THREADS 256
#define RPB 128
#define NCB 96                         // cols per block
#define KS 136                         // smem row stride (halfs) -> conflict-free

#define SM_XH 0
#define SM_WH (SM_XH + RPB * KS)                  // 17408
#define SM_WL (SM_WH + NCB * KS)                  // 30464
#define SM_END (SM_WL + NCB * KS)                 // 43520 halfs
#define PROJ_SMEM_BYTES (SM_END * 2 + NCB * 4)    // + fp32 bias

#define MMA3(acc, ra, rb)                                                        \
    asm volatile("mma.sync.aligned.m16n8k16.row.col.f32.f16.f16.f32 "            \
        "{%0,%1,%2,%3}, {%4,%5,%6,%7}, {%8,%9}, {%0,%1,%2,%3};"                  \
        : "+f"(acc[0]), "+f"(acc[1]), "+f"(acc[2]), "+f"(acc[3])                 \
        : "r"(ra[0]), "r"(ra[1]), "r"(ra[2]), "r"(ra[3]), "r"(rb[0]), "r"(rb[1]))

__global__ void __launch_bounds__(PROJ_THREADS, 2)
k_proj(const float* __restrict__ x,
       const float* __restrict__ bQ, const float* __restrict__ bK,
       const float* __restrict__ bV, float* __restrict__ out_v) {
    extern __shared__ __half sm[];
    float* bsm = (float*)(sm + SM_END);

    const int tid = threadIdx.x;
    const int row0 = blockIdx.x * RPB;
    const int c0 = blockIdx.y * NCB;

    // ---- stage W hi/lo for this col-half (uint4 = 8 halfs)
    {
        const uint4* wh_g = (const uint4*)g_wth;
        const uint4* wl_g = (const uint4*)g_wtl;
        for (int i = tid; i < NCB * D_IN / 8; i += PROJ_THREADS) {
            int m = i >> 4, c16 = i & 15;
            int gidx = (c0 + m) * 16 + c16;
            *(uint4*)(sm + SM_WH + m * KS + c16 * 8) = wh_g[gidx];
            *(uint4*)(sm + SM_WL + m * KS + c16 * 8) = wl_g[gidx];
        }
    }
    // ---- stage x -> fp16 (hi only)
    for (int i = tid; i < RPB * D_IN / 8; i += PROJ_THREADS) {
        int r = i >> 4, d8 = (i & 15) * 8;
        int row = row0 + r;
        __half hi[8];
        if (row < N_NODES) {
            const float4* xp = (const float4*)(x + (size_t)row * D_IN + d8);
            float4 v0 = xp[0], v1 = xp[1];
            hi[0] = __float2half_rn(v0.x); hi[1] = __float2half_rn(v0.y);
            hi[2] = __float2half_rn(v0.z); hi[3] = __float2half_rn(v0.w);
            hi[4] = __float2half_rn(v1.x); hi[5] = __float2half_rn(v1.y);
            hi[6] = __float2half_rn(v1.z); hi[7] = __float2half_rn(v1.w);
        } else {
#pragma unroll
            for (int t = 0; t < 8; t++) hi[t] = __float2half_rn(0.0f);
        }
        *(uint4*)(sm + SM_XH + r * KS + d8) = *(const uint4*)hi;
    }
    for (int i = tid; i < NCB; i += PROJ_THREADS) {
        int m = c0 + i;
        bsm[i] = (m < 64) ? bQ[m] : (m < 128 ? bK[m - 64] : bV[m - 128]);
    }
    __syncthreads();

    const int lane = tid & 31;
    const int wid  = tid >> 5;
    const int wm   = wid >> 2;        // 0..1
    const int wn   = wid & 3;         // 0..3
    const int grp  = lane >> 2;       // 0..7
    const int tig  = lane & 3;        // 0..3

    float acc[4][3][4];
#pragma unroll
    for (int mi = 0; mi < 4; mi++)
#pragma unroll
        for (int ni = 0; ni < 3; ni++)
#pragma unroll
            for (int t = 0; t < 4; t++) acc[mi][ni][t] = 0.0f;

    const int a_base = (wm * 64 + grp) * KS + tig * 2;
    const int b_base = (wn * 24 + grp) * KS + tig * 2;

#pragma unroll
    for (int k0 = 0; k0 < 8; k0++) {
        const int kc = k0 * 16;
        uint32_t bh[3][2], bl[3][2];
#pragma unroll
        for (int ni = 0; ni < 3; ni++) {
            int o = b_base + ni * 8 * KS + kc;
            bh[ni][0] = *(const uint32_t*)(sm + SM_WH + o);
            bh[ni][1] = *(const uint32_t*)(sm + SM_WH + o + 8);
            bl[ni][0] = *(const uint32_t*)(sm + SM_WL + o);
            bl[ni][1] = *(const uint32_t*)(sm + SM_WL + o + 8);
        }
        uint32_t ah[4][4];
#pragma unroll
        for (int mi = 0; mi < 4; mi++) {
            int o = a_base + mi * 16 * KS + kc;
            ah[mi][0] = *(const uint32_t*)(sm + SM_XH + o);
            ah[mi][1] = *(const uint32_t*)(sm + SM_XH + o + 8 * KS);
            ah[mi][2] = *(const uint32_t*)(sm + SM_XH + o + 8);
            ah[mi][3] = *(const uint32_t*)(sm + SM_XH + o + 8 * KS + 8);
        }
#pragma unroll
        for (int mi = 0; mi < 4; mi++)
#pragma unroll
            for (int ni = 0; ni < 3; ni++) {
                MMA3(acc[mi][ni], ah[mi], bh[ni]);
                MMA3(acc[mi][ni], ah[mi], bl[ni]);
            }
    }

    // ---- epilogue: bias + scatter (q/k fp16 scratch, v transposed fp32 out)
#pragma unroll
    for (int mi = 0; mi < 4; mi++) {
#pragma unroll
        for (int ni = 0; ni < 3; ni++) {
            int lc = wn * 24 + ni * 8 + tig * 2;
            int c = c0 + lc;
            float b0 = bsm[lc], b1 = bsm[lc + 1];
#pragma unroll
            for (int half = 0; half < 2; half++) {
                int r = row0 + wm * 64 + mi * 16 + grp + half * 8;
                if (r >= N_NODES) continue;
                float v0 = acc[mi][ni][half * 2 + 0] + b0;
                float v1 = acc[mi][ni][half * 2 + 1] + b1;
                if (c < 64) {
                    *(__half2*)(g_qh + r * 64 + c) = __floats2half2_rn(v0, v1);
                } else if (c < 128) {
                    *(__half2*)(g_kh + r * 64 + (c - 64)) = __floats2half2_rn(v0, v1);
                } else {
                    int cc = c - 128;
                    int h = cc >> 4, dd = cc & 15;
                    out_v[(size_t)r * 64 + dd * 4 + h] = v0;
                    out_v[(size_t)r * 64 + (dd + 1) * 4 + h] = v1;
                }
            }
        }
    }
}

// ---------------- edge pass 1: prods + segment exp-sums ----------------
// 8 lanes/edge; lane sub loads 16B of each 128B row; pair-reduce via shfl.
// Edges read directly from input (int64 or int32, uniform branch).
__global__ void k_edge1(const void* __restrict__ edge_raw,
                        float* __restrict__ out_prods) {
    int t = blockIdx.x * blockDim.x + threadIdx.x;
    int e = t >> 3;
    if (e >= N_EDGES) return;
    int sub = t & 7;

    int src, dst;
    if (g_is64) {
        const long long* ed = (const long long*)edge_raw;
        src = (int)ed[e];
        dst = (int)ed[N_EDGES + e];
    } else {
        const int* ed = (const int*)edge_raw;
        src = ed[e];
        dst = ed[N_EDGES + e];
    }

    uint4 qv = *(const uint4*)(g_qh + src * 64 + sub * 8);
    uint4 kv = *(const uint4*)(g_kh + dst * 64 + sub * 8);
    const __half2* qh = reinterpret_cast<const __half2*>(&qv);
    const __half2* kh = reinterpret_cast<const __half2*>(&kv);

    float dot = 0.0f;
#pragma unroll
    for (int i = 0; i < 4; i++) {
        float2 a = __half22float2(qh[i]);
        float2 b = __half22float2(kh[i]);
        dot = fmaf(a.x, b.x, dot);
        dot = fmaf(a.y, b.y, dot);
    }
    dot += __shfl_xor_sync(0xffffffffu, dot, 1);

    if ((sub & 1) == 0) {
        int h = sub >> 1;
        float p = dot * 0.25f;             // 1/sqrt(16)
        out_prods[e * 4 + h] = p;
        atomicAdd(&g_sum[src * 4 + h], __expf(p));
    }
}

// ---------------- edge pass 2: att = exp(prods) / sum[src] ----------------
__global__ void k_edge2(const void* __restrict__ edge_raw,
                        const float* __restrict__ out_prods,
                        float* __restrict__ out_att) {
    int e = blockIdx.x * blockDim.x + threadIdx.x;
    if (e >= N_EDGES) return;
    int src;
    if (g_is64) src = (int)((const long long*)edge_raw)[e];
    else        src = ((const int*)edge_raw)[e];

    float4 p = reinterpret_cast<const float4*>(out_prods)[e];
    float4 s = reinterpret_cast<const float4*>(g_sum)[src];
    float4 r;
    r.x = __fdividef(__expf(p.x), s.x + 1e-16f);
    r.y = __fdividef(__expf(p.y), s.y + 1e-16f);
    r.z = __fdividef(__expf(p.z), s.z + 1e-16f);
    r.w = __fdividef(__expf(p.w), s.w + 1e-16f);
    reinterpret_cast<float4*>(out_att)[e] = r;
}

// ---------------- launch ----------------
extern "C" void kernel_launch(void* const* d_in, const int* in_sizes, int n_in,
                              void* d_out, int out_size) {
    const float* x  = (const float*)d_in[0];
    const void*  edge = d_in[1];
    const float* WQ = (const float*)d_in[2];
    const float* bQ = (const float*)d_in[3];
    const float* WK = (const float*)d_in[4];
    const float* bK = (const float*)d_in[5];
    const float* WV = (const float*)d_in[6];
    const float* bV = (const float*)d_in[7];

    float* out       = (float*)d_out;
    float* out_att   = out;                                   // [E, 4]
    float* out_v     = out + (size_t)EH;                      // [N, 16, 4]
    float* out_prods = out_v + (size_t)N_NODES * ATT;         // [E, 4]

    cudaFuncSetAttribute(k_proj, cudaFuncAttributeMaxDynamicSharedMemorySize,
                         PROJ_SMEM_BYTES);

    k_detect<<<1, 256>>>((const int*)edge);
    k_zero<<<(NH + 255) / 256, 256>>>();
    k_wconv<<<(COLS * D_IN + 255) / 256, 256>>>(WQ, WK, WV);

    dim3 pg((N_NODES + RPB - 1) / RPB, 2);                    // (782, 2)
    k_proj<<<pg, PROJ_THREADS, PROJ_SMEM_BYTES>>>(x, bQ, bK, bV, out_v);

    int nt1 = N_EDGES * 8;
    k_edge1<<<(nt1 + 255) / 256, 256>>>(edge, out_prods);
    k_edge2<<<(N_EDGES + 255) / 256, 256>>>(edge, out_prods, out_att);
}

// round 5
// speedup vs baseline: 2.1870x; 1.0134x over previous
#include <cuda_runtime.h>
#include <cuda_fp16.h>
#include <cstdint>

#define N_NODES 100000
#define N_EDGES 3200000
#define D_IN 128
#define ATT 64
#define HEADS 4
#define NH (N_NODES * HEADS)
#define EH (N_EDGES * HEADS)
#define COLS 192

// ---------------- scratch (device globals; no allocation) ----------------
__device__ __align__(128) __half g_qh[(size_t)N_NODES * ATT];   // fp16 q rows (128B/row)
__device__ __align__(128) __half g_kh[(size_t)N_NODES * ATT];   // fp16 k rows
__device__ __align__(16)  float  g_sum[NH];
__device__ int g_is64;
// fused transposed weights, fp16 hi/lo split: Wt[m][d]
__device__ __align__(16) __half g_wth[COLS * D_IN];
__device__ __align__(16) __half g_wtl[COLS * D_IN];

// ---------------- edge dtype detection ----------------
__global__ void k_detect(const int* __restrict__ e32) {
    int any = 0;
    for (int i = threadIdx.x; i < 2048; i += blockDim.x)
        if (e32[2 * i + 1] != 0) any = 1;
    any = __syncthreads_or(any);
    if (threadIdx.x == 0) g_is64 = any ? 0 : 1;
}

// ---------------- zero segment sums ----------------
__global__ void k_zero() {
    int j = blockIdx.x * blockDim.x + threadIdx.x;
    if (j < NH) g_sum[j] = 0.0f;
}

// ---------------- W transpose + fp16 hi/lo split ----------------
__global__ void k_wconv(const float* __restrict__ WQ, const float* __restrict__ WK,
                        const float* __restrict__ WV) {
    int i = blockIdx.x * blockDim.x + threadIdx.x;   // over 192*128
    if (i >= COLS * D_IN) return;
    int m = i >> 7, d = i & 127;
    float w;
    if (m < 64)       w = WQ[d * 64 + m];
    else if (m < 128) w = WK[d * 64 + (m - 64)];
    else              w = WV[d * 64 + (m - 128)];
    __half hi = __float2half_rn(w);
    g_wth[i] = hi;
    g_wtl[i] = __float2half_rn(w - __half2float(hi));
}

// ---------------- HMMA 2-term split QKV projection (ldmatrix loads) -------
// Block: 128 rows x 96 cols, K=128. grid=(782,2). 256 threads = 8 warps
// (2M x 4N), warp tile 64x24 = 4x3 m16n8k16 tiles. D = Ah*(Bh + Bl).
#define PROJ_THREADS 256
#define RPB 128
#define NCB 96
#define KS 136                         // smem row stride (halfs); 272B -> LDSM conflict-free

#define SM_XH 0
#define SM_WH (SM_XH + RPB * KS)                  // 17408
#define SM_WL (SM_WH + NCB * KS)                  // 30464
#define SM_END (SM_WL + NCB * KS)                 // 43520 halfs
#define PROJ_SMEM_BYTES (SM_END * 2 + NCB * 4)

#define MMA3(acc, ra0, ra1, ra2, ra3, rb0, rb1)                                  \
    asm volatile("mma.sync.aligned.m16n8k16.row.col.f32.f16.f16.f32 "            \
        "{%0,%1,%2,%3}, {%4,%5,%6,%7}, {%8,%9}, {%0,%1,%2,%3};"                  \
        : "+f"(acc[0]), "+f"(acc[1]), "+f"(acc[2]), "+f"(acc[3])                 \
        : "r"(ra0), "r"(ra1), "r"(ra2), "r"(ra3), "r"(rb0), "r"(rb1))

#define LDSM_X4(r0, r1, r2, r3, addr)                                            \
    asm volatile("ldmatrix.sync.aligned.m8n8.x4.shared.b16 {%0,%1,%2,%3}, [%4];" \
        : "=r"(r0), "=r"(r1), "=r"(r2), "=r"(r3) : "r"(addr))

__global__ void __launch_bounds__(PROJ_THREADS, 2)
k_proj(const float* __restrict__ x,
       const float* __restrict__ bQ, const float* __restrict__ bK,
       const float* __restrict__ bV, float* __restrict__ out_v) {
    extern __shared__ __half sm[];
    float* bsm = (float*)(sm + SM_END);

    const int tid = threadIdx.x;
    const int row0 = blockIdx.x * RPB;
    const int c0 = blockIdx.y * NCB;

    // ---- stage W hi/lo for this col-half
    {
        const uint4* wh_g = (const uint4*)g_wth;
        const uint4* wl_g = (const uint4*)g_wtl;
        for (int i = tid; i < NCB * D_IN / 8; i += PROJ_THREADS) {
            int m = i >> 4, c16 = i & 15;
            int gidx = (c0 + m) * 16 + c16;
            *(uint4*)(sm + SM_WH + m * KS + c16 * 8) = wh_g[gidx];
            *(uint4*)(sm + SM_WL + m * KS + c16 * 8) = wl_g[gidx];
        }
    }
    // ---- stage x -> fp16
    for (int i = tid; i < RPB * D_IN / 8; i += PROJ_THREADS) {
        int r = i >> 4, d8 = (i & 15) * 8;
        int row = row0 + r;
        __half hi[8];
        if (row < N_NODES) {
            const float4* xp = (const float4*)(x + (size_t)row * D_IN + d8);
            float4 v0 = xp[0], v1 = xp[1];
            hi[0] = __float2half_rn(v0.x); hi[1] = __float2half_rn(v0.y);
            hi[2] = __float2half_rn(v0.z); hi[3] = __float2half_rn(v0.w);
            hi[4] = __float2half_rn(v1.x); hi[5] = __float2half_rn(v1.y);
            hi[6] = __float2half_rn(v1.z); hi[7] = __float2half_rn(v1.w);
        } else {
#pragma unroll
            for (int t = 0; t < 8; t++) hi[t] = __float2half_rn(0.0f);
        }
        *(uint4*)(sm + SM_XH + r * KS + d8) = *(const uint4*)hi;
    }
    for (int i = tid; i < NCB; i += PROJ_THREADS) {
        int m = c0 + i;
        bsm[i] = (m < 64) ? bQ[m] : (m < 128 ? bK[m - 64] : bV[m - 128]);
    }
    __syncthreads();

    const int lane = tid & 31;
    const int wid  = tid >> 5;
    const int wm   = wid >> 2;        // 0..1
    const int wn   = wid & 3;         // 0..3
    const int grp  = lane >> 2;       // 0..7
    const int tig  = lane & 3;        // 0..3

    float acc[4][3][4];
#pragma unroll
    for (int mi = 0; mi < 4; mi++)
#pragma unroll
        for (int ni = 0; ni < 3; ni++)
#pragma unroll
            for (int t = 0; t < 4; t++) acc[mi][ni][t] = 0.0f;

    // ldmatrix per-lane base addresses (in halfs, converted to bytes below)
    // A x4: lanes 0-15 -> m rows (lane&15) at k, lanes 16-31 -> same rows at k+8
    const int a_half = SM_XH + (wm * 64 + (lane & 15)) * KS + ((lane & 16) ? 8 : 0);
    // B x4: lanes 0-15 -> Wh rows (n = lane&7, k/k+8), lanes 16-31 -> Wl same
    const int b_half = ((lane & 16) ? SM_WL : SM_WH)
                     + (wn * 24 + (lane & 7)) * KS + ((lane & 8) ? 8 : 0);
    const uint32_t a_base = (uint32_t)__cvta_generic_to_shared(sm + a_half);
    const uint32_t b_base = (uint32_t)__cvta_generic_to_shared(sm + b_half);

#pragma unroll
    for (int k0 = 0; k0 < 8; k0++) {
        const uint32_t kb = k0 * 32;           // 16 halfs = 32 bytes
        uint32_t bh[3][2], bl[3][2];
#pragma unroll
        for (int ni = 0; ni < 3; ni++)
            LDSM_X4(bh[ni][0], bh[ni][1], bl[ni][0], bl[ni][1],
                    b_base + ni * (8 * KS * 2) + kb);
        uint32_t a[4][4];
#pragma unroll
        for (int mi = 0; mi < 4; mi++)
            LDSM_X4(a[mi][0], a[mi][1], a[mi][2], a[mi][3],
                    a_base + mi * (16 * KS * 2) + kb);
#pragma unroll
        for (int mi = 0; mi < 4; mi++)
#pragma unroll
            for (int ni = 0; ni < 3; ni++) {
                MMA3(acc[mi][ni], a[mi][0], a[mi][1], a[mi][2], a[mi][3],
                     bh[ni][0], bh[ni][1]);
                MMA3(acc[mi][ni], a[mi][0], a[mi][1], a[mi][2], a[mi][3],
                     bl[ni][0], bl[ni][1]);
            }
    }

    // ---- epilogue: bias + scatter (q/k fp16 scratch, v transposed fp32 out)
#pragma unroll
    for (int mi = 0; mi < 4; mi++) {
#pragma unroll
        for (int ni = 0; ni < 3; ni++) {
            int lc = wn * 24 + ni * 8 + tig * 2;
            int c = c0 + lc;
            float b0 = bsm[lc], b1 = bsm[lc + 1];
#pragma unroll
            for (int half = 0; half < 2; half++) {
                int r = row0 + wm * 64 + mi * 16 + grp + half * 8;
                if (r >= N_NODES) continue;
                float v0 = acc[mi][ni][half * 2 + 0] + b0;
                float v1 = acc[mi][ni][half * 2 + 1] + b1;
                if (c < 64) {
                    *(__half2*)(g_qh + r * 64 + c) = __floats2half2_rn(v0, v1);
                } else if (c < 128) {
                    *(__half2*)(g_kh + r * 64 + (c - 64)) = __floats2half2_rn(v0, v1);
                } else {
                    int cc = c - 128;
                    int h = cc >> 4, dd = cc & 15;
                    out_v[(size_t)r * 64 + dd * 4 + h] = v0;
                    out_v[(size_t)r * 64 + (dd + 1) * 4 + h] = v1;
                }
            }
        }
    }
}

// ---------------- edge pass 1: prods + segment exp-sums ----------------
// 8 lanes/edge; lane sub loads 16B of each 128B row. Dot accumulated in
// fp16 (HMUL2/HFMA2 chain of 4), reduced in f32 + shfl.
__global__ void k_edge1(const void* __restrict__ edge_raw,
                        float* __restrict__ out_prods) {
    int t = blockIdx.x * blockDim.x + threadIdx.x;
    int e = t >> 3;
    if (e >= N_EDGES) return;
    int sub = t & 7;

    int src, dst;
    if (g_is64) {
        const long long* ed = (const long long*)edge_raw;
        src = (int)ed[e];
        dst = (int)ed[N_EDGES + e];
    } else {
        const int* ed = (const int*)edge_raw;
        src = ed[e];
        dst = ed[N_EDGES + e];
    }

    uint4 qv = *(const uint4*)(g_qh + src * 64 + sub * 8);
    uint4 kv = *(const uint4*)(g_kh + dst * 64 + sub * 8);
    const __half2* qh = reinterpret_cast<const __half2*>(&qv);
    const __half2* kh = reinterpret_cast<const __half2*>(&kv);

    __half2 acch = __hmul2(qh[0], kh[0]);
    acch = __hfma2(qh[1], kh[1], acch);
    acch = __hfma2(qh[2], kh[2], acch);
    acch = __hfma2(qh[3], kh[3], acch);
    float dot = __low2float(acch) + __high2float(acch);
    dot += __shfl_xor_sync(0xffffffffu, dot, 1);

    if ((sub & 1) == 0) {
        int h = sub >> 1;
        float p = dot * 0.25f;             // 1/sqrt(16)
        out_prods[e * 4 + h] = p;
        atomicAdd(&g_sum[src * 4 + h], __expf(p));
    }
}

// ---------------- edge pass 2: att = exp(prods) / sum[src] ----------------
__global__ void k_edge2(const void* __restrict__ edge_raw,
                        const float* __restrict__ out_prods,
                        float* __restrict__ out_att) {
    int e = blockIdx.x * blockDim.x + threadIdx.x;
    if (e >= N_EDGES) return;
    int src;
    if (g_is64) src = (int)((const long long*)edge_raw)[e];
    else        src = ((const int*)edge_raw)[e];

    float4 p = reinterpret_cast<const float4*>(out_prods)[e];
    float4 s = reinterpret_cast<const float4*>(g_sum)[src];
    float4 r;
    r.x = __fdividef(__expf(p.x), s.x + 1e-16f);
    r.y = __fdividef(__expf(p.y), s.y + 1e-16f);
    r.z = __fdividef(__expf(p.z), s.z + 1e-16f);
    r.w = __fdividef(__expf(p.w), s.w + 1e-16f);
    reinterpret_cast<float4*>(out_att)[e] = r;
}

// ---------------- launch ----------------
extern "C" void kernel_launch(void* const* d_in, const int* in_sizes, int n_in,
                              void* d_out, int out_size) {
    const float* x  = (const float*)d_in[0];
    const void*  edge = d_in[1];
    const float* WQ = (const float*)d_in[2];
    const float* bQ = (const float*)d_in[3];
    const float* WK = (const float*)d_in[4];
    const float* bK = (const float*)d_in[5];
    const float* WV = (const float*)d_in[6];
    const float* bV = (const float*)d_in[7];

    float* out       = (float*)d_out;
    float* out_att   = out;                                   // [E, 4]
    float* out_v     = out + (size_t)EH;                      // [N, 16, 4]
    float* out_prods = out_v + (size_t)N_NODES * ATT;         // [E, 4]

    cudaFuncSetAttribute(k_proj, cudaFuncAttributeMaxDynamicSharedMemorySize,
                         PROJ_SMEM_BYTES);

    k_detect<<<1, 256>>>((const int*)edge);
    k_zero<<<(NH + 255) / 256, 256>>>();
    k_wconv<<<(COLS * D_IN + 255) / 256, 256>>>(WQ, WK, WV);

    dim3 pg((N_NODES + RPB - 1) / RPB, 2);                    // (782, 2)
    k_proj<<<pg, PROJ_THREADS, PROJ_SMEM_BYTES>>>(x, bQ, bK, bV, out_v);

    int nt1 = N_EDGES * 8;
    k_edge1<<<(nt1 + 255) / 256, 256>>>(edge, out_prods);
    k_edge2<<<(N_EDGES + 255) / 256, 256>>>(edge, out_prods, out_att);
}

// round 6
// speedup vs baseline: 2.2281x; 1.0188x over previous
#include <cuda_runtime.h>
#include <cuda_fp16.h>
#include <cstdint>

#define N_NODES 100000
#define N_EDGES 3200000
#define D_IN 128
#define ATT 64
#define HEADS 4
#define NH (N_NODES * HEADS)
#define EH (N_EDGES * HEADS)
#define COLS 192

// ---------------- scratch (device globals; no allocation) ----------------
__device__ __align__(128) __half g_qh[(size_t)N_NODES * ATT];   // fp16 q rows (128B/row)
__device__ __align__(128) __half g_kh[(size_t)N_NODES * ATT];   // fp16 k rows
__device__ __align__(128) __half g_xh[(size_t)N_NODES * D_IN];  // fp16 x (precomputed)
__device__ __align__(16)  float  g_sum[NH];
__device__ int g_is64;
// fused transposed weights, fp16 hi/lo split: Wt[m][d]
__device__ __align__(16) __half g_wth[COLS * D_IN];
__device__ __align__(16) __half g_wtl[COLS * D_IN];

// ---------------- edge dtype detection ----------------
__global__ void k_detect(const int* __restrict__ e32) {
    int any = 0;
    for (int i = threadIdx.x; i < 2048; i += blockDim.x)
        if (e32[2 * i + 1] != 0) any = 1;
    any = __syncthreads_or(any);
    if (threadIdx.x == 0) g_is64 = any ? 0 : 1;
}

// ---------------- zero segment sums ----------------
__global__ void k_zero() {
    int j = blockIdx.x * blockDim.x + threadIdx.x;
    if (j < NH) g_sum[j] = 0.0f;
}

// ---------------- W transpose + fp16 hi/lo split ----------------
__global__ void k_wconv(const float* __restrict__ WQ, const float* __restrict__ WK,
                        const float* __restrict__ WV) {
    int i = blockIdx.x * blockDim.x + threadIdx.x;   // over 192*128
    if (i >= COLS * D_IN) return;
    int m = i >> 7, d = i & 127;
    float w;
    if (m < 64)       w = WQ[d * 64 + m];
    else if (m < 128) w = WK[d * 64 + (m - 64)];
    else              w = WV[d * 64 + (m - 128)];
    __half hi = __float2half_rn(w);
    g_wth[i] = hi;
    g_wtl[i] = __float2half_rn(w - __half2float(hi));
}

// ---------------- x -> fp16 precompute (coalesced) ----------------
__global__ void k_xh(const float* __restrict__ x) {
    int i = blockIdx.x * blockDim.x + threadIdx.x;   // chunk of 8 elems
    const int NCHUNK = N_NODES * D_IN / 8;
    if (i >= NCHUNK) return;
    const float4* xp = (const float4*)(x + (size_t)i * 8);
    float4 v0 = xp[0], v1 = xp[1];
    __half hi[8];
    hi[0] = __float2half_rn(v0.x); hi[1] = __float2half_rn(v0.y);
    hi[2] = __float2half_rn(v0.z); hi[3] = __float2half_rn(v0.w);
    hi[4] = __float2half_rn(v1.x); hi[5] = __float2half_rn(v1.y);
    hi[6] = __float2half_rn(v1.z); hi[7] = __float2half_rn(v1.w);
    ((uint4*)g_xh)[i] = *(const uint4*)hi;
}

// ---------------- HMMA 2-term split QKV projection ----------------
// Block: 128 rows x 48 cols, K=128. grid=(782,4). 256 threads = 8 warps
// (4M x 2N): warp tile 32 rows x 24 cols = 2x3 m16n8k16 tiles.
// D = Ah*(Bh + Bl). 61KB smem -> 3 CTAs/SM.
#define PROJ_THREADS 256
#define RPB 128
#define NCB 48
#define KS 136                         // smem row stride (halfs); conflict-free LDSM

#define SM_XH 0
#define SM_WH (SM_XH + RPB * KS)                  // 17408
#define SM_WL (SM_WH + NCB * KS)                  // 23936
#define SM_END (SM_WL + NCB * KS)                 // 30464 halfs
#define PROJ_SMEM_BYTES (SM_END * 2 + NCB * 4)

#define MMA3(acc, ra0, ra1, ra2, ra3, rb0, rb1)                                  \
    asm volatile("mma.sync.aligned.m16n8k16.row.col.f32.f16.f16.f32 "            \
        "{%0,%1,%2,%3}, {%4,%5,%6,%7}, {%8,%9}, {%0,%1,%2,%3};"                  \
        : "+f"(acc[0]), "+f"(acc[1]), "+f"(acc[2]), "+f"(acc[3])                 \
        : "r"(ra0), "r"(ra1), "r"(ra2), "r"(ra3), "r"(rb0), "r"(rb1))

#define LDSM_X4(r0, r1, r2, r3, addr)                                            \
    asm volatile("ldmatrix.sync.aligned.m8n8.x4.shared.b16 {%0,%1,%2,%3}, [%4];" \
        : "=r"(r0), "=r"(r1), "=r"(r2), "=r"(r3) : "r"(addr))

__global__ void __launch_bounds__(PROJ_THREADS, 3)
k_proj(const float* __restrict__ bQ, const float* __restrict__ bK,
       const float* __restrict__ bV, float* __restrict__ out_v) {
    extern __shared__ __half sm[];
    float* bsm = (float*)(sm + SM_END);

    const int tid = threadIdx.x;
    const int row0 = blockIdx.x * RPB;
    const int c0 = blockIdx.y * NCB;

    // ---- stage W hi/lo for this col slice (uint4 = 8 halfs)
    {
        const uint4* wh_g = (const uint4*)g_wth;
        const uint4* wl_g = (const uint4*)g_wtl;
        for (int i = tid; i < NCB * D_IN / 8; i += PROJ_THREADS) {
            int m = i >> 4, c16 = i & 15;
            int gidx = (c0 + m) * 16 + c16;
            *(uint4*)(sm + SM_WH + m * KS + c16 * 8) = wh_g[gidx];
            *(uint4*)(sm + SM_WL + m * KS + c16 * 8) = wl_g[gidx];
        }
    }
    // ---- stage xh (already fp16)
    {
        const uint4* xh_g = (const uint4*)g_xh;
        const uint4 z = make_uint4(0, 0, 0, 0);
        for (int i = tid; i < RPB * D_IN / 8; i += PROJ_THREADS) {
            int r = i >> 4, c16 = i & 15;
            int row = row0 + r;
            uint4 v = (row < N_NODES) ? xh_g[row * 16 + c16] : z;
            *(uint4*)(sm + SM_XH + r * KS + c16 * 8) = v;
        }
    }
    for (int i = tid; i < NCB; i += PROJ_THREADS) {
        int m = c0 + i;
        bsm[i] = (m < 64) ? bQ[m] : (m < 128 ? bK[m - 64] : bV[m - 128]);
    }
    __syncthreads();

    const int lane = tid & 31;
    const int wid  = tid >> 5;
    const int wm   = wid & 3;         // 0..3  (32-row strip)
    const int wn   = wid >> 2;        // 0..1  (24-col strip)
    const int grp  = lane >> 2;       // 0..7
    const int tig  = lane & 3;        // 0..3

    float acc[2][3][4];
#pragma unroll
    for (int mi = 0; mi < 2; mi++)
#pragma unroll
        for (int ni = 0; ni < 3; ni++)
#pragma unroll
            for (int t = 0; t < 4; t++) acc[mi][ni][t] = 0.0f;

    // A x4: lanes 0-15 -> rows (lane&15), lanes 16-31 -> same rows, k+8
    const int a_half = SM_XH + (wm * 32 + (lane & 15)) * KS + ((lane & 16) ? 8 : 0);
    // B x4 packed hi/lo: lanes 0-15 Wh (n=lane&7, k/k+8), lanes 16-31 Wl
    const int b_half = ((lane & 16) ? SM_WL : SM_WH)
                     + (wn * 24 + (lane & 7)) * KS + ((lane & 8) ? 8 : 0);
    const uint32_t a_base = (uint32_t)__cvta_generic_to_shared(sm + a_half);
    const uint32_t b_base = (uint32_t)__cvta_generic_to_shared(sm + b_half);

#pragma unroll
    for (int k0 = 0; k0 < 8; k0++) {
        const uint32_t kb = k0 * 32;           // 16 halfs = 32 bytes
        uint32_t bh[3][2], bl[3][2];
#pragma unroll
        for (int ni = 0; ni < 3; ni++)
            LDSM_X4(bh[ni][0], bh[ni][1], bl[ni][0], bl[ni][1],
                    b_base + ni * (8 * KS * 2) + kb);
        uint32_t a[2][4];
#pragma unroll
        for (int mi = 0; mi < 2; mi++)
            LDSM_X4(a[mi][0], a[mi][1], a[mi][2], a[mi][3],
                    a_base + mi * (16 * KS * 2) + kb);
#pragma unroll
        for (int mi = 0; mi < 2; mi++)
#pragma unroll
            for (int ni = 0; ni < 3; ni++) {
                MMA3(acc[mi][ni], a[mi][0], a[mi][1], a[mi][2], a[mi][3],
                     bh[ni][0], bh[ni][1]);
                MMA3(acc[mi][ni], a[mi][0], a[mi][1], a[mi][2], a[mi][3],
                     bl[ni][0], bl[ni][1]);
            }
    }

    // ---- epilogue: bias + scatter (q/k fp16 scratch, v transposed fp32 out)
#pragma unroll
    for (int mi = 0; mi < 2; mi++) {
#pragma unroll
        for (int ni = 0; ni < 3; ni++) {
            int lc = wn * 24 + ni * 8 + tig * 2;
            int c = c0 + lc;
            float b0 = bsm[lc], b1 = bsm[lc + 1];
#pragma unroll
            for (int half = 0; half < 2; half++) {
                int r = row0 + wm * 32 + mi * 16 + grp + half * 8;
                if (r >= N_NODES) continue;
                float v0 = acc[mi][ni][half * 2 + 0] + b0;
                float v1 = acc[mi][ni][half * 2 + 1] + b1;
                if (c < 64) {
                    *(__half2*)(g_qh + r * 64 + c) = __floats2half2_rn(v0, v1);
                } else if (c < 128) {
                    *(__half2*)(g_kh + r * 64 + (c - 64)) = __floats2half2_rn(v0, v1);
                } else {
                    int cc = c - 128;
                    int h = cc >> 4, dd = cc & 15;
                    out_v[(size_t)r * 64 + dd * 4 + h] = v0;
                    out_v[(size_t)r * 64 + (dd + 1) * 4 + h] = v1;
                }
            }
        }
    }
}

// ---------------- edge pass 1: prods + segment exp-sums ----------------
// 8 lanes/edge; lane sub loads 16B of each 128B row. fp16 dot + f32 reduce.
__global__ void k_edge1(const void* __restrict__ edge_raw,
                        float* __restrict__ out_prods) {
    int t = blockIdx.x * blockDim.x + threadIdx.x;
    int e = t >> 3;
    if (e >= N_EDGES) return;
    int sub = t & 7;

    int src, dst;
    if (g_is64) {
        const long long* ed = (const long long*)edge_raw;
        src = (int)ed[e];
        dst = (int)ed[N_EDGES + e];
    } else {
        const int* ed = (const int*)edge_raw;
        src = ed[e];
        dst = ed[N_EDGES + e];
    }

    uint4 qv = *(const uint4*)(g_qh + src * 64 + sub * 8);
    uint4 kv = *(const uint4*)(g_kh + dst * 64 + sub * 8);
    const __half2* qh = reinterpret_cast<const __half2*>(&qv);
    const __half2* kh = reinterpret_cast<const __half2*>(&kv);

    __half2 acch = __hmul2(qh[0], kh[0]);
    acch = __hfma2(qh[1], kh[1], acch);
    acch = __hfma2(qh[2], kh[2], acch);
    acch = __hfma2(qh[3], kh[3], acch);
    float dot = __low2float(acch) + __high2float(acch);
    dot += __shfl_xor_sync(0xffffffffu, dot, 1);

    if ((sub & 1) == 0) {
        int h = sub >> 1;
        float p = dot * 0.25f;             // 1/sqrt(16)
        out_prods[e * 4 + h] = p;
        atomicAdd(&g_sum[src * 4 + h], __expf(p));
    }
}

// ---------------- edge pass 2: att = exp(prods) / sum[src] ----------------
__global__ void k_edge2(const void* __restrict__ edge_raw,
                        const float* __restrict__ out_prods,
                        float* __restrict__ out_att) {
    int e = blockIdx.x * blockDim.x + threadIdx.x;
    if (e >= N_EDGES) return;
    int src;
    if (g_is64) src = (int)((const long long*)edge_raw)[e];
    else        src = ((const int*)edge_raw)[e];

    float4 p = reinterpret_cast<const float4*>(out_prods)[e];
    float4 s = reinterpret_cast<const float4*>(g_sum)[src];
    float4 r;
    r.x = __fdividef(__expf(p.x), s.x + 1e-16f);
    r.y = __fdividef(__expf(p.y), s.y + 1e-16f);
    r.z = __fdividef(__expf(p.z), s.z + 1e-16f);
    r.w = __fdividef(__expf(p.w), s.w + 1e-16f);
    reinterpret_cast<float4*>(out_att)[e] = r;
}

// ---------------- launch ----------------
extern "C" void kernel_launch(void* const* d_in, const int* in_sizes, int n_in,
                              void* d_out, int out_size) {
    const float* x  = (const float*)d_in[0];
    const void*  edge = d_in[1];
    const float* WQ = (const float*)d_in[2];
    const float* bQ = (const float*)d_in[3];
    const float* WK = (const float*)d_in[4];
    const float* bK = (const float*)d_in[5];
    const float* WV = (const float*)d_in[6];
    const float* bV = (const float*)d_in[7];

    float* out       = (float*)d_out;
    float* out_att   = out;                                   // [E, 4]
    float* out_v     = out + (size_t)EH;                      // [N, 16, 4]
    float* out_prods = out_v + (size_t)N_NODES * ATT;         // [E, 4]

    cudaFuncSetAttribute(k_proj, cudaFuncAttributeMaxDynamicSharedMemorySize,
                         PROJ_SMEM_BYTES);

    k_detect<<<1, 256>>>((const int*)edge);
    k_zero<<<(NH + 255) / 256, 256>>>();
    k_wconv<<<(COLS * D_IN + 255) / 256, 256>>>(WQ, WK, WV);
    k_xh<<<(N_NODES * D_IN / 8 + 255) / 256, 256>>>(x);

    dim3 pg((N_NODES + RPB - 1) / RPB, 4);                    // (782, 4)
    k_proj<<<pg, PROJ_THREADS, PROJ_SMEM_BYTES>>>(bQ, bK, bV, out_v);

    int nt1 = N_EDGES * 8;
    k_edge1<<<(nt1 + 255) / 256, 256>>>(edge, out_prods);
    k_edge2<<<(N_EDGES + 255) / 256, 256>>>(edge, out_prods, out_att);
}

// round 7
// speedup vs baseline: 2.6439x; 1.1866x over previous
#include <cuda_runtime.h>
#include <cuda_fp16.h>
#include <cstdint>

#define N_NODES 100000
#define N_EDGES 3200000
#define D_IN 128
#define ATT 64
#define HEADS 4
#define NH (N_NODES * HEADS)
#define EH (N_EDGES * HEADS)
#define COLS 192
#define EHALF (N_EDGES / 2)

// ---------------- scratch (device globals; no allocation) ----------------
__device__ __align__(128) __half g_qh[(size_t)N_NODES * ATT];   // fp16 q rows (128B/row)
__device__ __align__(128) __half g_kh[(size_t)N_NODES * ATT];   // fp16 k rows
__device__ __align__(128) __half g_xh[(size_t)N_NODES * D_IN];  // fp16 x (precomputed)
__device__ __align__(16)  float  g_sum[NH];
__device__ int g_is64;
// fused transposed weights, fp16 hi/lo split: Wt[m][d]
__device__ __align__(16) __half g_wth[COLS * D_IN];
__device__ __align__(16) __half g_wtl[COLS * D_IN];

// ---------------- edge dtype detection ----------------
__global__ void k_detect(const int* __restrict__ e32) {
    int any = 0;
    for (int i = threadIdx.x; i < 2048; i += blockDim.x)
        if (e32[2 * i + 1] != 0) any = 1;
    any = __syncthreads_or(any);
    if (threadIdx.x == 0) g_is64 = any ? 0 : 1;
}

// ---------------- zero segment sums ----------------
__global__ void k_zero() {
    int j = blockIdx.x * blockDim.x + threadIdx.x;
    if (j < NH) g_sum[j] = 0.0f;
}

// ---------------- W transpose + fp16 hi/lo split ----------------
__global__ void k_wconv(const float* __restrict__ WQ, const float* __restrict__ WK,
                        const float* __restrict__ WV) {
    int i = blockIdx.x * blockDim.x + threadIdx.x;   // over 192*128
    if (i >= COLS * D_IN) return;
    int m = i >> 7, d = i & 127;
    float w;
    if (m < 64)       w = WQ[d * 64 + m];
    else if (m < 128) w = WK[d * 64 + (m - 64)];
    else              w = WV[d * 64 + (m - 128)];
    __half hi = __float2half_rn(w);
    g_wth[i] = hi;
    g_wtl[i] = __float2half_rn(w - __half2float(hi));
}

// ---------------- x -> fp16 precompute (coalesced) ----------------
__global__ void k_xh(const float* __restrict__ x) {
    int i = blockIdx.x * blockDim.x + threadIdx.x;   // chunk of 8 elems
    const int NCHUNK = N_NODES * D_IN / 8;
    if (i >= NCHUNK) return;
    const float4* xp = (const float4*)(x + (size_t)i * 8);
    float4 v0 = xp[0], v1 = xp[1];
    __half hi[8];
    hi[0] = __float2half_rn(v0.x); hi[1] = __float2half_rn(v0.y);
    hi[2] = __float2half_rn(v0.z); hi[3] = __float2half_rn(v0.w);
    hi[4] = __float2half_rn(v1.x); hi[5] = __float2half_rn(v1.y);
    hi[6] = __float2half_rn(v1.z); hi[7] = __float2half_rn(v1.w);
    ((uint4*)g_xh)[i] = *(const uint4*)hi;
}

// ---------------- HMMA 2-term split QKV projection ----------------
// Block: 128 rows x 48 cols, K=128. grid=(782,4). 256 threads = 8 warps
// (4M x 2N): warp tile 32x24 = 2x3 m16n8k16 tiles. D = Ah*(Bh + Bl).
#define PROJ_THREADS 256
#define RPB 128
#define NCB 48
#define KS 136

#define SM_XH 0
#define SM_WH (SM_XH + RPB * KS)
#define SM_WL (SM_WH + NCB * KS)
#define SM_END (SM_WL + NCB * KS)
#define PROJ_SMEM_BYTES (SM_END * 2 + NCB * 4)

#define MMA3(acc, ra0, ra1, ra2, ra3, rb0, rb1)                                  \
    asm volatile("mma.sync.aligned.m16n8k16.row.col.f32.f16.f16.f32 "            \
        "{%0,%1,%2,%3}, {%4,%5,%6,%7}, {%8,%9}, {%0,%1,%2,%3};"                  \
        : "+f"(acc[0]), "+f"(acc[1]), "+f"(acc[2]), "+f"(acc[3])                 \
        : "r"(ra0), "r"(ra1), "r"(ra2), "r"(ra3), "r"(rb0), "r"(rb1))

#define LDSM_X4(r0, r1, r2, r3, addr)                                            \
    asm volatile("ldmatrix.sync.aligned.m8n8.x4.shared.b16 {%0,%1,%2,%3}, [%4];" \
        : "=r"(r0), "=r"(r1), "=r"(r2), "=r"(r3) : "r"(addr))

__global__ void __launch_bounds__(PROJ_THREADS, 3)
k_proj(const float* __restrict__ bQ, const float* __restrict__ bK,
       const float* __restrict__ bV, float* __restrict__ out_v) {
    extern __shared__ __half sm[];
    float* bsm = (float*)(sm + SM_END);

    const int tid = threadIdx.x;
    const int row0 = blockIdx.x * RPB;
    const int c0 = blockIdx.y * NCB;

    {
        const uint4* wh_g = (const uint4*)g_wth;
        const uint4* wl_g = (const uint4*)g_wtl;
        for (int i = tid; i < NCB * D_IN / 8; i += PROJ_THREADS) {
            int m = i >> 4, c16 = i & 15;
            int gidx = (c0 + m) * 16 + c16;
            *(uint4*)(sm + SM_WH + m * KS + c16 * 8) = wh_g[gidx];
            *(uint4*)(sm + SM_WL + m * KS + c16 * 8) = wl_g[gidx];
        }
    }
    {
        const uint4* xh_g = (const uint4*)g_xh;
        const uint4 z = make_uint4(0, 0, 0, 0);
        for (int i = tid; i < RPB * D_IN / 8; i += PROJ_THREADS) {
            int r = i >> 4, c16 = i & 15;
            int row = row0 + r;
            uint4 v = (row < N_NODES) ? xh_g[row * 16 + c16] : z;
            *(uint4*)(sm + SM_XH + r * KS + c16 * 8) = v;
        }
    }
    for (int i = tid; i < NCB; i += PROJ_THREADS) {
        int m = c0 + i;
        bsm[i] = (m < 64) ? bQ[m] : (m < 128 ? bK[m - 64] : bV[m - 128]);
    }
    __syncthreads();

    const int lane = tid & 31;
    const int wid  = tid >> 5;
    const int wm   = wid & 3;
    const int wn   = wid >> 2;
    const int grp  = lane >> 2;
    const int tig  = lane & 3;

    float acc[2][3][4];
#pragma unroll
    for (int mi = 0; mi < 2; mi++)
#pragma unroll
        for (int ni = 0; ni < 3; ni++)
#pragma unroll
            for (int t = 0; t < 4; t++) acc[mi][ni][t] = 0.0f;

    const int a_half = SM_XH + (wm * 32 + (lane & 15)) * KS + ((lane & 16) ? 8 : 0);
    const int b_half = ((lane & 16) ? SM_WL : SM_WH)
                     + (wn * 24 + (lane & 7)) * KS + ((lane & 8) ? 8 : 0);
    const uint32_t a_base = (uint32_t)__cvta_generic_to_shared(sm + a_half);
    const uint32_t b_base = (uint32_t)__cvta_generic_to_shared(sm + b_half);

#pragma unroll
    for (int k0 = 0; k0 < 8; k0++) {
        const uint32_t kb = k0 * 32;
        uint32_t bh[3][2], bl[3][2];
#pragma unroll
        for (int ni = 0; ni < 3; ni++)
            LDSM_X4(bh[ni][0], bh[ni][1], bl[ni][0], bl[ni][1],
                    b_base + ni * (8 * KS * 2) + kb);
        uint32_t a[2][4];
#pragma unroll
        for (int mi = 0; mi < 2; mi++)
            LDSM_X4(a[mi][0], a[mi][1], a[mi][2], a[mi][3],
                    a_base + mi * (16 * KS * 2) + kb);
#pragma unroll
        for (int mi = 0; mi < 2; mi++)
#pragma unroll
            for (int ni = 0; ni < 3; ni++) {
                MMA3(acc[mi][ni], a[mi][0], a[mi][1], a[mi][2], a[mi][3],
                     bh[ni][0], bh[ni][1]);
                MMA3(acc[mi][ni], a[mi][0], a[mi][1], a[mi][2], a[mi][3],
                     bl[ni][0], bl[ni][1]);
            }
    }

#pragma unroll
    for (int mi = 0; mi < 2; mi++) {
#pragma unroll
        for (int ni = 0; ni < 3; ni++) {
            int lc = wn * 24 + ni * 8 + tig * 2;
            int c = c0 + lc;
            float b0 = bsm[lc], b1 = bsm[lc + 1];
#pragma unroll
            for (int half = 0; half < 2; half++) {
                int r = row0 + wm * 32 + mi * 16 + grp + half * 8;
                if (r >= N_NODES) continue;
                float v0 = acc[mi][ni][half * 2 + 0] + b0;
                float v1 = acc[mi][ni][half * 2 + 1] + b1;
                if (c < 64) {
                    *(__half2*)(g_qh + r * 64 + c) = __floats2half2_rn(v0, v1);
                } else if (c < 128) {
                    *(__half2*)(g_kh + r * 64 + (c - 64)) = __floats2half2_rn(v0, v1);
                } else {
                    int cc = c - 128;
                    int h = cc >> 4, dd = cc & 15;
                    out_v[(size_t)r * 64 + dd * 4 + h] = v0;
                    out_v[(size_t)r * 64 + (dd + 1) * 4 + h] = v1;
                }
            }
        }
    }
}

// ---------------- edge pass 1: prods + segment exp-sums (2 edges/thread) ----
// 8 lanes per edge-pair (e0 = p, e1 = p + E/2). Each thread runs TWO
// independent gather chains -> 4 outstanding 128B loads, 2x latency hiding.
__global__ void k_edge1(const void* __restrict__ edge_raw,
                        float* __restrict__ out_prods) {
    int t = blockIdx.x * blockDim.x + threadIdx.x;
    int p = t >> 3;
    if (p >= EHALF) return;
    int sub = t & 7;
    int e0 = p, e1 = p + EHALF;

    int src0, dst0, src1, dst1;
    if (g_is64) {
        const long long* ed = (const long long*)edge_raw;
        src0 = (int)ed[e0];           dst0 = (int)ed[N_EDGES + e0];
        src1 = (int)ed[e1];           dst1 = (int)ed[N_EDGES + e1];
    } else {
        const int* ed = (const int*)edge_raw;
        src0 = ed[e0];                dst0 = ed[N_EDGES + e0];
        src1 = ed[e1];                dst1 = ed[N_EDGES + e1];
    }

    uint4 qv0 = *(const uint4*)(g_qh + src0 * 64 + sub * 8);
    uint4 kv0 = *(const uint4*)(g_kh + dst0 * 64 + sub * 8);
    uint4 qv1 = *(const uint4*)(g_qh + src1 * 64 + sub * 8);
    uint4 kv1 = *(const uint4*)(g_kh + dst1 * 64 + sub * 8);

    const __half2* q0 = reinterpret_cast<const __half2*>(&qv0);
    const __half2* k0 = reinterpret_cast<const __half2*>(&kv0);
    const __half2* q1 = reinterpret_cast<const __half2*>(&qv1);
    const __half2* k1 = reinterpret_cast<const __half2*>(&kv1);

    __half2 a0 = __hmul2(q0[0], k0[0]);
    a0 = __hfma2(q0[1], k0[1], a0);
    a0 = __hfma2(q0[2], k0[2], a0);
    a0 = __hfma2(q0[3], k0[3], a0);
    __half2 a1 = __hmul2(q1[0], k1[0]);
    a1 = __hfma2(q1[1], k1[1], a1);
    a1 = __hfma2(q1[2], k1[2], a1);
    a1 = __hfma2(q1[3], k1[3], a1);

    float dot0 = __low2float(a0) + __high2float(a0);
    float dot1 = __low2float(a1) + __high2float(a1);
    dot0 += __shfl_xor_sync(0xffffffffu, dot0, 1);
    dot1 += __shfl_xor_sync(0xffffffffu, dot1, 1);

    if ((sub & 1) == 0) {
        int h = sub >> 1;
        float p0 = dot0 * 0.25f;           // 1/sqrt(16)
        float p1 = dot1 * 0.25f;
        out_prods[e0 * 4 + h] = p0;
        out_prods[e1 * 4 + h] = p1;
        atomicAdd(&g_sum[src0 * 4 + h], __expf(p0));
        atomicAdd(&g_sum[src1 * 4 + h], __expf(p1));
    }
}

// ---------------- edge pass 2: att = exp(prods) / sum[src] (2 edges/thread) -
__global__ void k_edge2(const void* __restrict__ edge_raw,
                        const float* __restrict__ out_prods,
                        float* __restrict__ out_att) {
    int p = blockIdx.x * blockDim.x + threadIdx.x;
    if (p >= EHALF) return;
    int e0 = p, e1 = p + EHALF;

    int src0, src1;
    if (g_is64) {
        const long long* ed = (const long long*)edge_raw;
        src0 = (int)ed[e0];
        src1 = (int)ed[e1];
    } else {
        const int* ed = (const int*)edge_raw;
        src0 = ed[e0];
        src1 = ed[e1];
    }

    float4 p0 = reinterpret_cast<const float4*>(out_prods)[e0];
    float4 p1 = reinterpret_cast<const float4*>(out_prods)[e1];
    float4 s0 = reinterpret_cast<const float4*>(g_sum)[src0];
    float4 s1 = reinterpret_cast<const float4*>(g_sum)[src1];

    float4 r0, r1;
    r0.x = __fdividef(__expf(p0.x), s0.x + 1e-16f);
    r0.y = __fdividef(__expf(p0.y), s0.y + 1e-16f);
    r0.z = __fdividef(__expf(p0.z), s0.z + 1e-16f);
    r0.w = __fdividef(__expf(p0.w), s0.w + 1e-16f);
    r1.x = __fdividef(__expf(p1.x), s1.x + 1e-16f);
    r1.y = __fdividef(__expf(p1.y), s1.y + 1e-16f);
    r1.z = __fdividef(__expf(p1.z), s1.z + 1e-16f);
    r1.w = __fdividef(__expf(p1.w), s1.w + 1e-16f);
    reinterpret_cast<float4*>(out_att)[e0] = r0;
    reinterpret_cast<float4*>(out_att)[e1] = r1;
}

// ---------------- launch ----------------
extern "C" void kernel_launch(void* const* d_in, const int* in_sizes, int n_in,
                              void* d_out, int out_size) {
    const float* x  = (const float*)d_in[0];
    const void*  edge = d_in[1];
    const float* WQ = (const float*)d_in[2];
    const float* bQ = (const float*)d_in[3];
    const float* WK = (const float*)d_in[4];
    const float* bK = (const float*)d_in[5];
    const float* WV = (const float*)d_in[6];
    const float* bV = (const float*)d_in[7];

    float* out       = (float*)d_out;
    float* out_att   = out;                                   // [E, 4]
    float* out_v     = out + (size_t)EH;                      // [N, 16, 4]
    float* out_prods = out_v + (size_t)N_NODES * ATT;         // [E, 4]

    cudaFuncSetAttribute(k_proj, cudaFuncAttributeMaxDynamicSharedMemorySize,
                         PROJ_SMEM_BYTES);

    k_detect<<<1, 256>>>((const int*)edge);
    k_zero<<<(NH + 255) / 256, 256>>>();
    k_wconv<<<(COLS * D_IN + 255) / 256, 256>>>(WQ, WK, WV);
    k_xh<<<(N_NODES * D_IN / 8 + 255) / 256, 256>>>(x);

    dim3 pg((N_NODES + RPB - 1) / RPB, 4);                    // (782, 4)
    k_proj<<<pg, PROJ_THREADS, PROJ_SMEM_BYTES>>>(bQ, bK, bV, out_v);

    int nt1 = EHALF * 8;
    k_edge1<<<(nt1 + 255) / 256, 256>>>(edge, out_prods);
    k_edge2<<<(EHALF + 255) / 256, 256>>>(edge, out_prods, out_att);
}

// round 8
// speedup vs baseline: 2.8295x; 1.0702x over previous
#include <cuda_runtime.h>
#include <cuda_fp16.h>
#include <cstdint>

#define N_NODES 100000
#define N_EDGES 3200000
#define D_IN 128
#define ATT 64
#define HEADS 4
#define NH (N_NODES * HEADS)
#define EH (N_EDGES * HEADS)
#define COLS 192
#define EQ (N_EDGES / 4)

// ---------------- scratch (device globals; no allocation) ----------------
__device__ __align__(128) __half g_qh[(size_t)N_NODES * ATT];   // fp16 q rows (128B/row)
__device__ __align__(128) __half g_kh[(size_t)N_NODES * ATT];   // fp16 k rows
__device__ __align__(128) __half g_xh[(size_t)N_NODES * D_IN];  // fp16 x (precomputed)
__device__ __align__(16)  float  g_sum[NH];
__device__ int g_is64;
// fused transposed weights, fp16 hi/lo split: Wt[m][d]
__device__ __align__(16) __half g_wth[COLS * D_IN];
__device__ __align__(16) __half g_wtl[COLS * D_IN];

// ---------------- fused prep: xh | zero | wconv | detect (one launch) ------
#define XH_BLOCKS   (N_NODES * D_IN / 8 / 256)          // 6250 (exact)
#define ZERO_BLOCKS ((NH + 255) / 256)                  // 1563
#define WC_BLOCKS   ((COLS * D_IN + 255) / 256)         // 96
#define PREP_BLOCKS (XH_BLOCKS + ZERO_BLOCKS + WC_BLOCKS + 1)

__global__ void k_prep(const float* __restrict__ x,
                       const float* __restrict__ WQ, const float* __restrict__ WK,
                       const float* __restrict__ WV, const int* __restrict__ e32) {
    int b = blockIdx.x;
    if (b < XH_BLOCKS) {
        // ---- x -> fp16 (chunk of 8 elems per thread)
        int i = b * 256 + threadIdx.x;
        const float4* xp = (const float4*)(x + (size_t)i * 8);
        float4 v0 = xp[0], v1 = xp[1];
        __half hi[8];
        hi[0] = __float2half_rn(v0.x); hi[1] = __float2half_rn(v0.y);
        hi[2] = __float2half_rn(v0.z); hi[3] = __float2half_rn(v0.w);
        hi[4] = __float2half_rn(v1.x); hi[5] = __float2half_rn(v1.y);
        hi[6] = __float2half_rn(v1.z); hi[7] = __float2half_rn(v1.w);
        ((uint4*)g_xh)[i] = *(const uint4*)hi;
    } else if (b < XH_BLOCKS + ZERO_BLOCKS) {
        int j = (b - XH_BLOCKS) * 256 + threadIdx.x;
        if (j < NH) g_sum[j] = 0.0f;
    } else if (b < XH_BLOCKS + ZERO_BLOCKS + WC_BLOCKS) {
        int i = (b - XH_BLOCKS - ZERO_BLOCKS) * 256 + threadIdx.x;
        if (i < COLS * D_IN) {
            int m = i >> 7, d = i & 127;
            float w;
            if (m < 64)       w = WQ[d * 64 + m];
            else if (m < 128) w = WK[d * 64 + (m - 64)];
            else              w = WV[d * 64 + (m - 128)];
            __half hi = __float2half_rn(w);
            g_wth[i] = hi;
            g_wtl[i] = __float2half_rn(w - __half2float(hi));
        }
    } else {
        // ---- edge dtype detect: int64 edges (<1e5) have zero high words
        int any = 0;
        for (int i = threadIdx.x; i < 2048; i += 256)
            if (e32[2 * i + 1] != 0) any = 1;
        any = __syncthreads_or(any);
        if (threadIdx.x == 0) g_is64 = any ? 0 : 1;
    }
}

// ---------------- HMMA 2-term split QKV projection ----------------
// Block: 128 rows x 48 cols, K=128. grid=(782,4). 256 threads = 8 warps
// (4M x 2N): warp tile 32x24 = 2x3 m16n8k16 tiles. D = Ah*(Bh + Bl).
#define PROJ_THREADS 256
#define RPB 128
#define NCB 48
#define KS 136

#define SM_XH 0
#define SM_WH (SM_XH + RPB * KS)
#define SM_WL (SM_WH + NCB * KS)
#define SM_END (SM_WL + NCB * KS)
#define PROJ_SMEM_BYTES (SM_END * 2 + NCB * 4)

#define MMA3(acc, ra0, ra1, ra2, ra3, rb0, rb1)                                  \
    asm volatile("mma.sync.aligned.m16n8k16.row.col.f32.f16.f16.f32 "            \
        "{%0,%1,%2,%3}, {%4,%5,%6,%7}, {%8,%9}, {%0,%1,%2,%3};"                  \
        : "+f"(acc[0]), "+f"(acc[1]), "+f"(acc[2]), "+f"(acc[3])                 \
        : "r"(ra0), "r"(ra1), "r"(ra2), "r"(ra3), "r"(rb0), "r"(rb1))

#define LDSM_X4(r0, r1, r2, r3, addr)                                            \
    asm volatile("ldmatrix.sync.aligned.m8n8.x4.shared.b16 {%0,%1,%2,%3}, [%4];" \
        : "=r"(r0), "=r"(r1), "=r"(r2), "=r"(r3) : "r"(addr))

__global__ void __launch_bounds__(PROJ_THREADS, 3)
k_proj(const float* __restrict__ bQ, const float* __restrict__ bK,
       const float* __restrict__ bV, float* __restrict__ out_v) {
    extern __shared__ __half sm[];
    float* bsm = (float*)(sm + SM_END);

    const int tid = threadIdx.x;
    const int row0 = blockIdx.x * RPB;
    const int c0 = blockIdx.y * NCB;

    {
        const uint4* wh_g = (const uint4*)g_wth;
        const uint4* wl_g = (const uint4*)g_wtl;
        for (int i = tid; i < NCB * D_IN / 8; i += PROJ_THREADS) {
            int m = i >> 4, c16 = i & 15;
            int gidx = (c0 + m) * 16 + c16;
            *(uint4*)(sm + SM_WH + m * KS + c16 * 8) = wh_g[gidx];
            *(uint4*)(sm + SM_WL + m * KS + c16 * 8) = wl_g[gidx];
        }
    }
    {
        const uint4* xh_g = (const uint4*)g_xh;
        const uint4 z = make_uint4(0, 0, 0, 0);
        for (int i = tid; i < RPB * D_IN / 8; i += PROJ_THREADS) {
            int r = i >> 4, c16 = i & 15;
            int row = row0 + r;
            uint4 v = (row < N_NODES) ? xh_g[row * 16 + c16] : z;
            *(uint4*)(sm + SM_XH + r * KS + c16 * 8) = v;
        }
    }
    for (int i = tid; i < NCB; i += PROJ_THREADS) {
        int m = c0 + i;
        bsm[i] = (m < 64) ? bQ[m] : (m < 128 ? bK[m - 64] : bV[m - 128]);
    }
    __syncthreads();

    const int lane = tid & 31;
    const int wid  = tid >> 5;
    const int wm   = wid & 3;
    const int wn   = wid >> 2;
    const int grp  = lane >> 2;
    const int tig  = lane & 3;

    float acc[2][3][4];
#pragma unroll
    for (int mi = 0; mi < 2; mi++)
#pragma unroll
        for (int ni = 0; ni < 3; ni++)
#pragma unroll
            for (int t = 0; t < 4; t++) acc[mi][ni][t] = 0.0f;

    const int a_half = SM_XH + (wm * 32 + (lane & 15)) * KS + ((lane & 16) ? 8 : 0);
    const int b_half = ((lane & 16) ? SM_WL : SM_WH)
                     + (wn * 24 + (lane & 7)) * KS + ((lane & 8) ? 8 : 0);
    const uint32_t a_base = (uint32_t)__cvta_generic_to_shared(sm + a_half);
    const uint32_t b_base = (uint32_t)__cvta_generic_to_shared(sm + b_half);

#pragma unroll
    for (int k0 = 0; k0 < 8; k0++) {
        const uint32_t kb = k0 * 32;
        uint32_t bh[3][2], bl[3][2];
#pragma unroll
        for (int ni = 0; ni < 3; ni++)
            LDSM_X4(bh[ni][0], bh[ni][1], bl[ni][0], bl[ni][1],
                    b_base + ni * (8 * KS * 2) + kb);
        uint32_t a[2][4];
#pragma unroll
        for (int mi = 0; mi < 2; mi++)
            LDSM_X4(a[mi][0], a[mi][1], a[mi][2], a[mi][3],
                    a_base + mi * (16 * KS * 2) + kb);
#pragma unroll
        for (int mi = 0; mi < 2; mi++)
#pragma unroll
            for (int ni = 0; ni < 3; ni++) {
                MMA3(acc[mi][ni], a[mi][0], a[mi][1], a[mi][2], a[mi][3],
                     bh[ni][0], bh[ni][1]);
                MMA3(acc[mi][ni], a[mi][0], a[mi][1], a[mi][2], a[mi][3],
                     bl[ni][0], bl[ni][1]);
            }
    }

#pragma unroll
    for (int mi = 0; mi < 2; mi++) {
#pragma unroll
        for (int ni = 0; ni < 3; ni++) {
            int lc = wn * 24 + ni * 8 + tig * 2;
            int c = c0 + lc;
            float b0 = bsm[lc], b1 = bsm[lc + 1];
#pragma unroll
            for (int half = 0; half < 2; half++) {
                int r = row0 + wm * 32 + mi * 16 + grp + half * 8;
                if (r >= N_NODES) continue;
                float v0 = acc[mi][ni][half * 2 + 0] + b0;
                float v1 = acc[mi][ni][half * 2 + 1] + b1;
                if (c < 64) {
                    *(__half2*)(g_qh + r * 64 + c) = __floats2half2_rn(v0, v1);
                } else if (c < 128) {
                    *(__half2*)(g_kh + r * 64 + (c - 64)) = __floats2half2_rn(v0, v1);
                } else {
                    int cc = c - 128;
                    int h = cc >> 4, dd = cc & 15;
                    out_v[(size_t)r * 64 + dd * 4 + h] = v0;
                    out_v[(size_t)r * 64 + (dd + 1) * 4 + h] = v1;
                }
            }
        }
    }
}

// ---------------- edge pass 1: prods + segment exp-sums (4 edges/thread) ----
// 8 lanes per edge-quad (e_i = p + i*E/4). 8 independent 128B gather chains
// per thread keep the L2 pipeline full.
__global__ void k_edge1(const void* __restrict__ edge_raw,
                        float* __restrict__ out_prods) {
    int t = blockIdx.x * blockDim.x + threadIdx.x;
    int p = t >> 3;
    if (p >= EQ) return;
    int sub = t & 7;

    int src[4], dst[4];
    if (g_is64) {
        const long long* ed = (const long long*)edge_raw;
#pragma unroll
        for (int i = 0; i < 4; i++) {
            src[i] = (int)ed[p + i * EQ];
            dst[i] = (int)ed[N_EDGES + p + i * EQ];
        }
    } else {
        const int* ed = (const int*)edge_raw;
#pragma unroll
        for (int i = 0; i < 4; i++) {
            src[i] = ed[p + i * EQ];
            dst[i] = ed[N_EDGES + p + i * EQ];
        }
    }

    uint4 qv[4], kv[4];
#pragma unroll
    for (int i = 0; i < 4; i++) {
        qv[i] = *(const uint4*)(g_qh + src[i] * 64 + sub * 8);
        kv[i] = *(const uint4*)(g_kh + dst[i] * 64 + sub * 8);
    }

    float dot[4];
#pragma unroll
    for (int i = 0; i < 4; i++) {
        const __half2* q = reinterpret_cast<const __half2*>(&qv[i]);
        const __half2* k = reinterpret_cast<const __half2*>(&kv[i]);
        __half2 a = __hmul2(q[0], k[0]);
        a = __hfma2(q[1], k[1], a);
        a = __hfma2(q[2], k[2], a);
        a = __hfma2(q[3], k[3], a);
        float d = __low2float(a) + __high2float(a);
        dot[i] = d + __shfl_xor_sync(0xffffffffu, d, 1);
    }

    if ((sub & 1) == 0) {
        int h = sub >> 1;
#pragma unroll
        for (int i = 0; i < 4; i++) {
            float pr = dot[i] * 0.25f;         // 1/sqrt(16)
            out_prods[(p + i * EQ) * 4 + h] = pr;
            atomicAdd(&g_sum[src[i] * 4 + h], __expf(pr));
        }
    }
}

// ---------------- edge pass 2: att = exp(prods)/sum[src] (4 edges/thread) ---
__global__ void k_edge2(const void* __restrict__ edge_raw,
                        const float* __restrict__ out_prods,
                        float* __restrict__ out_att) {
    int p = blockIdx.x * blockDim.x + threadIdx.x;
    if (p >= EQ) return;

    int src[4];
    if (g_is64) {
        const long long* ed = (const long long*)edge_raw;
#pragma unroll
        for (int i = 0; i < 4; i++) src[i] = (int)ed[p + i * EQ];
    } else {
        const int* ed = (const int*)edge_raw;
#pragma unroll
        for (int i = 0; i < 4; i++) src[i] = ed[p + i * EQ];
    }

    float4 pr[4], s[4];
#pragma unroll
    for (int i = 0; i < 4; i++) {
        pr[i] = reinterpret_cast<const float4*>(out_prods)[p + i * EQ];
        s[i]  = reinterpret_cast<const float4*>(g_sum)[src[i]];
    }
#pragma unroll
    for (int i = 0; i < 4; i++) {
        float4 r;
        r.x = __fdividef(__expf(pr[i].x), s[i].x + 1e-16f);
        r.y = __fdividef(__expf(pr[i].y), s[i].y + 1e-16f);
        r.z = __fdividef(__expf(pr[i].z), s[i].z + 1e-16f);
        r.w = __fdividef(__expf(pr[i].w), s[i].w + 1e-16f);
        reinterpret_cast<float4*>(out_att)[p + i * EQ] = r;
    }
}

// ---------------- launch ----------------
extern "C" void kernel_launch(void* const* d_in, const int* in_sizes, int n_in,
                              void* d_out, int out_size) {
    const float* x  = (const float*)d_in[0];
    const void*  edge = d_in[1];
    const float* WQ = (const float*)d_in[2];
    const float* bQ = (const float*)d_in[3];
    const float* WK = (const float*)d_in[4];
    const float* bK = (const float*)d_in[5];
    const float* WV = (const float*)d_in[6];
    const float* bV = (const float*)d_in[7];

    float* out       = (float*)d_out;
    float* out_att   = out;                                   // [E, 4]
    float* out_v     = out + (size_t)EH;                      // [N, 16, 4]
    float* out_prods = out_v + (size_t)N_NODES * ATT;         // [E, 4]

    cudaFuncSetAttribute(k_proj, cudaFuncAttributeMaxDynamicSharedMemorySize,
                         PROJ_SMEM_BYTES);

    k_prep<<<PREP_BLOCKS, 256>>>(x, WQ, WK, WV, (const int*)edge);

    dim3 pg((N_NODES + RPB - 1) / RPB, 4);                    // (782, 4)
    k_proj<<<pg, PROJ_THREADS, PROJ_SMEM_BYTES>>>(bQ, bK, bV, out_v);

    int nt1 = EQ * 8;
    k_edge1<<<(nt1 + 255) / 256, 256>>>(edge, out_prods);
    k_edge2<<<(EQ + 255) / 256, 256>>>(edge, out_prods, out_att);
}

// round 9
// speedup vs baseline: 2.9832x; 1.0543x over previous
#include <cuda_runtime.h>
#include <cuda_fp16.h>
#include <cstdint>

#define N_NODES 100000
#define N_EDGES 3200000
#define D_IN 128
#define ATT 64
#define HEADS 4
#define NH (N_NODES * HEADS)
#define EH (N_EDGES * HEADS)
#define COLS 192
#define EQ (N_EDGES / 4)

// ---------------- scratch (device globals; no allocation) ----------------
__device__ __align__(128) __half g_qh[(size_t)N_NODES * ATT];   // fp16 q rows (128B/row)
__device__ __align__(128) __half g_kh[(size_t)N_NODES * ATT];   // fp16 k rows
__device__ __align__(128) __half g_xh[(size_t)N_NODES * D_IN];  // fp16 x (precomputed)
__device__ __align__(16)  float  g_sum[NH];
__device__ int g_is64;
// fused transposed weights fp16: Wt[m][d]
__device__ __align__(16) __half g_wth[COLS * D_IN];

// ---------------- fused prep: xh | zero | wconv | detect (one launch) ------
#define XH_BLOCKS   (N_NODES * D_IN / 8 / 256)          // 6250 (exact)
#define ZERO_BLOCKS ((NH + 255) / 256)                  // 1563
#define WC_BLOCKS   ((COLS * D_IN + 255) / 256)         // 96
#define PREP_BLOCKS (XH_BLOCKS + ZERO_BLOCKS + WC_BLOCKS + 1)

__global__ void k_prep(const float* __restrict__ x,
                       const float* __restrict__ WQ, const float* __restrict__ WK,
                       const float* __restrict__ WV, const int* __restrict__ e32) {
    int b = blockIdx.x;
    if (b < XH_BLOCKS) {
        // ---- x -> fp16 (chunk of 8 elems per thread)
        int i = b * 256 + threadIdx.x;
        const float4* xp = (const float4*)(x + (size_t)i * 8);
        float4 v0 = xp[0], v1 = xp[1];
        __half hi[8];
        hi[0] = __float2half_rn(v0.x); hi[1] = __float2half_rn(v0.y);
        hi[2] = __float2half_rn(v0.z); hi[3] = __float2half_rn(v0.w);
        hi[4] = __float2half_rn(v1.x); hi[5] = __float2half_rn(v1.y);
        hi[6] = __float2half_rn(v1.z); hi[7] = __float2half_rn(v1.w);
        ((uint4*)g_xh)[i] = *(const uint4*)hi;
    } else if (b < XH_BLOCKS + ZERO_BLOCKS) {
        int j = (b - XH_BLOCKS) * 256 + threadIdx.x;
        if (j < NH) g_sum[j] = 0.0f;
    } else if (b < XH_BLOCKS + ZERO_BLOCKS + WC_BLOCKS) {
        int i = (b - XH_BLOCKS - ZERO_BLOCKS) * 256 + threadIdx.x;
        if (i < COLS * D_IN) {
            int m = i >> 7, d = i & 127;
            float w;
            if (m < 64)       w = WQ[d * 64 + m];
            else if (m < 128) w = WK[d * 64 + (m - 64)];
            else              w = WV[d * 64 + (m - 128)];
            g_wth[i] = __float2half_rn(w);
        }
    } else {
        // ---- edge dtype detect: int64 edges (<1e5) have zero high words
        int any = 0;
        for (int i = threadIdx.x; i < 2048; i += 256)
            if (e32[2 * i + 1] != 0) any = 1;
        any = __syncthreads_or(any);
        if (threadIdx.x == 0) g_is64 = any ? 0 : 1;
    }
}

// ---------------- HMMA fp16 QKV projection (single term) ----------------
// Block: 128 rows x 48 cols, K=128. grid=(782,4). 256 threads = 8 warps
// (4M x 2N): warp tile 32x24 = 2x3 m16n8k16 tiles. 47KB smem -> 4 CTAs/SM.
#define PROJ_THREADS 256
#define RPB 128
#define NCB 48
#define KS 136

#define SM_XH 0
#define SM_WH (SM_XH + RPB * KS)
#define SM_END (SM_WH + NCB * KS)
#define PROJ_SMEM_BYTES (SM_END * 2 + NCB * 4)

#define MMA3(acc, ra0, ra1, ra2, ra3, rb0, rb1)                                  \
    asm volatile("mma.sync.aligned.m16n8k16.row.col.f32.f16.f16.f32 "            \
        "{%0,%1,%2,%3}, {%4,%5,%6,%7}, {%8,%9}, {%0,%1,%2,%3};"                  \
        : "+f"(acc[0]), "+f"(acc[1]), "+f"(acc[2]), "+f"(acc[3])                 \
        : "r"(ra0), "r"(ra1), "r"(ra2), "r"(ra3), "r"(rb0), "r"(rb1))

#define LDSM_X4(r0, r1, r2, r3, addr)                                            \
    asm volatile("ldmatrix.sync.aligned.m8n8.x4.shared.b16 {%0,%1,%2,%3}, [%4];" \
        : "=r"(r0), "=r"(r1), "=r"(r2), "=r"(r3) : "r"(addr))

#define LDSM_X2(r0, r1, addr)                                                    \
    asm volatile("ldmatrix.sync.aligned.m8n8.x2.shared.b16 {%0,%1}, [%2];"       \
        : "=r"(r0), "=r"(r1) : "r"(addr))

__global__ void __launch_bounds__(PROJ_THREADS, 4)
k_proj(const float* __restrict__ bQ, const float* __restrict__ bK,
       const float* __restrict__ bV, float* __restrict__ out_v) {
    extern __shared__ __half sm[];
    float* bsm = (float*)(sm + SM_END);

    const int tid = threadIdx.x;
    const int row0 = blockIdx.x * RPB;
    const int c0 = blockIdx.y * NCB;

    {
        const uint4* wh_g = (const uint4*)g_wth;
        for (int i = tid; i < NCB * D_IN / 8; i += PROJ_THREADS) {
            int m = i >> 4, c16 = i & 15;
            *(uint4*)(sm + SM_WH + m * KS + c16 * 8) = wh_g[(c0 + m) * 16 + c16];
        }
    }
    {
        const uint4* xh_g = (const uint4*)g_xh;
        const uint4 z = make_uint4(0, 0, 0, 0);
        for (int i = tid; i < RPB * D_IN / 8; i += PROJ_THREADS) {
            int r = i >> 4, c16 = i & 15;
            int row = row0 + r;
            uint4 v = (row < N_NODES) ? xh_g[row * 16 + c16] : z;
            *(uint4*)(sm + SM_XH + r * KS + c16 * 8) = v;
        }
    }
    for (int i = tid; i < NCB; i += PROJ_THREADS) {
        int m = c0 + i;
        bsm[i] = (m < 64) ? bQ[m] : (m < 128 ? bK[m - 64] : bV[m - 128]);
    }
    __syncthreads();

    const int lane = tid & 31;
    const int wid  = tid >> 5;
    const int wm   = wid & 3;
    const int wn   = wid >> 2;
    const int grp  = lane >> 2;
    const int tig  = lane & 3;

    float acc[2][3][4];
#pragma unroll
    for (int mi = 0; mi < 2; mi++)
#pragma unroll
        for (int ni = 0; ni < 3; ni++)
#pragma unroll
            for (int t = 0; t < 4; t++) acc[mi][ni][t] = 0.0f;

    // A x4: lanes 0-15 rows (lane&15) at k, lanes 16-31 same rows at k+8
    const int a_half = SM_XH + (wm * 32 + (lane & 15)) * KS + ((lane & 16) ? 8 : 0);
    // B x2: lanes 0-7 rows n at k, lanes 8-15 rows n at k+8 (lanes 16-31 unused)
    const int b_half = SM_WH + (wn * 24 + (lane & 7)) * KS + ((lane & 8) ? 8 : 0);
    const uint32_t a_base = (uint32_t)__cvta_generic_to_shared(sm + a_half);
    const uint32_t b_base = (uint32_t)__cvta_generic_to_shared(sm + b_half);

#pragma unroll
    for (int k0 = 0; k0 < 8; k0++) {
        const uint32_t kb = k0 * 32;
        uint32_t b[3][2];
#pragma unroll
        for (int ni = 0; ni < 3; ni++)
            LDSM_X2(b[ni][0], b[ni][1], b_base + ni * (8 * KS * 2) + kb);
        uint32_t a[2][4];
#pragma unroll
        for (int mi = 0; mi < 2; mi++)
            LDSM_X4(a[mi][0], a[mi][1], a[mi][2], a[mi][3],
                    a_base + mi * (16 * KS * 2) + kb);
#pragma unroll
        for (int mi = 0; mi < 2; mi++)
#pragma unroll
            for (int ni = 0; ni < 3; ni++)
                MMA3(acc[mi][ni], a[mi][0], a[mi][1], a[mi][2], a[mi][3],
                     b[ni][0], b[ni][1]);
    }

#pragma unroll
    for (int mi = 0; mi < 2; mi++) {
#pragma unroll
        for (int ni = 0; ni < 3; ni++) {
            int lc = wn * 24 + ni * 8 + tig * 2;
            int c = c0 + lc;
            float b0 = bsm[lc], b1 = bsm[lc + 1];
#pragma unroll
            for (int half = 0; half < 2; half++) {
                int r = row0 + wm * 32 + mi * 16 + grp + half * 8;
                if (r >= N_NODES) continue;
                float v0 = acc[mi][ni][half * 2 + 0] + b0;
                float v1 = acc[mi][ni][half * 2 + 1] + b1;
                if (c < 64) {
                    *(__half2*)(g_qh + r * 64 + c) = __floats2half2_rn(v0, v1);
                } else if (c < 128) {
                    *(__half2*)(g_kh + r * 64 + (c - 64)) = __floats2half2_rn(v0, v1);
                } else {
                    int cc = c - 128;
                    int h = cc >> 4, dd = cc & 15;
                    out_v[(size_t)r * 64 + dd * 4 + h] = v0;
                    out_v[(size_t)r * 64 + (dd + 1) * 4 + h] = v1;
                }
            }
        }
    }
}

// ---------------- edge pass 1: prods + segment exp-sums (4 edges/thread) ----
__global__ void k_edge1(const void* __restrict__ edge_raw,
                        float* __restrict__ out_prods) {
    int t = blockIdx.x * blockDim.x + threadIdx.x;
    int p = t >> 3;
    if (p >= EQ) return;
    int sub = t & 7;

    int src[4], dst[4];
    if (g_is64) {
        const long long* ed = (const long long*)edge_raw;
#pragma unroll
        for (int i = 0; i < 4; i++) {
            src[i] = (int)ed[p + i * EQ];
            dst[i] = (int)ed[N_EDGES + p + i * EQ];
        }
    } else {
        const int* ed = (const int*)edge_raw;
#pragma unroll
        for (int i = 0; i < 4; i++) {
            src[i] = ed[p + i * EQ];
            dst[i] = ed[N_EDGES + p + i * EQ];
        }
    }

    uint4 qv[4], kv[4];
#pragma unroll
    for (int i = 0; i < 4; i++) {
        qv[i] = *(const uint4*)(g_qh + src[i] * 64 + sub * 8);
        kv[i] = *(const uint4*)(g_kh + dst[i] * 64 + sub * 8);
    }

    float dot[4];
#pragma unroll
    for (int i = 0; i < 4; i++) {
        const __half2* q = reinterpret_cast<const __half2*>(&qv[i]);
        const __half2* k = reinterpret_cast<const __half2*>(&kv[i]);
        __half2 a = __hmul2(q[0], k[0]);
        a = __hfma2(q[1], k[1], a);
        a = __hfma2(q[2], k[2], a);
        a = __hfma2(q[3], k[3], a);
        float d = __low2float(a) + __high2float(a);
        dot[i] = d + __shfl_xor_sync(0xffffffffu, d, 1);
    }

    if ((sub & 1) == 0) {
        int h = sub >> 1;
#pragma unroll
        for (int i = 0; i < 4; i++) {
            float pr = dot[i] * 0.25f;         // 1/sqrt(16)
            out_prods[(p + i * EQ) * 4 + h] = pr;
            atomicAdd(&g_sum[src[i] * 4 + h], __expf(pr));
        }
    }
}

// ---------------- edge pass 2: att = exp(prods)/sum[src] (4 edges/thread) ---
__global__ void k_edge2(const void* __restrict__ edge_raw,
                        const float* __restrict__ out_prods,
                        float* __restrict__ out_att) {
    int p = blockIdx.x * blockDim.x + threadIdx.x;
    if (p >= EQ) return;

    int src[4];
    if (g_is64) {
        const long long* ed = (const long long*)edge_raw;
#pragma unroll
        for (int i = 0; i < 4; i++) src[i] = (int)ed[p + i * EQ];
    } else {
        const int* ed = (const int*)edge_raw;
#pragma unroll
        for (int i = 0; i < 4; i++) src[i] = ed[p + i * EQ];
    }

    float4 pr[4], s[4];
#pragma unroll
    for (int i = 0; i < 4; i++) {
        pr[i] = reinterpret_cast<const float4*>(out_prods)[p + i * EQ];
        s[i]  = reinterpret_cast<const float4*>(g_sum)[src[i]];
    }
#pragma unroll
    for (int i = 0; i < 4; i++) {
        float4 r;
        r.x = __fdividef(__expf(pr[i].x), s[i].x + 1e-16f);
        r.y = __fdividef(__expf(pr[i].y), s[i].y + 1e-16f);
        r.z = __fdividef(__expf(pr[i].z), s[i].z + 1e-16f);
        r.w = __fdividef(__expf(pr[i].w), s[i].w + 1e-16f);
        reinterpret_cast<float4*>(out_att)[p + i * EQ] = r;
    }
}

// ---------------- launch ----------------
extern "C" void kernel_launch(void* const* d_in, const int* in_sizes, int n_in,
                              void* d_out, int out_size) {
    const float* x  = (const float*)d_in[0];
    const void*  edge = d_in[1];
    const float* WQ = (const float*)d_in[2];
    const float* bQ = (const float*)d_in[3];
    const float* WK = (const float*)d_in[4];
    const float* bK = (const float*)d_in[5];
    const float* WV = (const float*)d_in[6];
    const float* bV = (const float*)d_in[7];

    float* out       = (float*)d_out;
    float* out_att   = out;                                   // [E, 4]
    float* out_v     = out + (size_t)EH;                      // [N, 16, 4]
    float* out_prods = out_v + (size_t)N_NODES * ATT;         // [E, 4]

    cudaFuncSetAttribute(k_proj, cudaFuncAttributeMaxDynamicSharedMemorySize,
                         PROJ_SMEM_BYTES);

    k_prep<<<PREP_BLOCKS, 256>>>(x, WQ, WK, WV, (const int*)edge);

    dim3 pg((N_NODES + RPB - 1) / RPB, 4);                    // (782, 4)
    k_proj<<<pg, PROJ_THREADS, PROJ_SMEM_BYTES>>>(bQ, bK, bV, out_v);

    int nt1 = EQ * 8;
    k_edge1<<<(nt1 + 255) / 256, 256>>>(edge, out_prods);
    k_edge2<<<(EQ + 255) / 256, 256>>>(edge, out_prods, out_att);
}

// round 10
// speedup vs baseline: 3.0713x; 1.0295x over previous
#include <cuda_runtime.h>
#include <cuda_fp16.h>
#include <cstdint>

#define N_NODES 100000
#define N_EDGES 3200000
#define D_IN 128
#define ATT 64
#define HEADS 4
#define NH (N_NODES * HEADS)
#define EH (N_EDGES * HEADS)
#define COLS 192
#define EQ (N_EDGES / 4)

// ---------------- scratch (device globals; no allocation) ----------------
__device__ __align__(128) __half g_qh[(size_t)N_NODES * ATT];   // fp16 q rows (128B/row)
__device__ __align__(128) __half g_kh[(size_t)N_NODES * ATT];   // fp16 k rows
__device__ __align__(128) __half g_xh[(size_t)N_NODES * D_IN];  // fp16 x (precomputed)
__device__ __align__(16)  float  g_sum[NH];
__device__ int g_is64;
// fused transposed weights fp16: Wt[m][d]
__device__ __align__(16) __half g_wth[COLS * D_IN];

// ---------------- fused prep: xh | zero | wconv | detect (one launch) ------
#define XH_BLOCKS   (N_NODES * D_IN / 8 / 256)          // 6250 (exact)
#define ZERO_BLOCKS ((NH + 255) / 256)                  // 1563
#define WC_BLOCKS   ((COLS * D_IN + 255) / 256)         // 96
#define PREP_BLOCKS (XH_BLOCKS + ZERO_BLOCKS + WC_BLOCKS + 1)

__global__ void k_prep(const float* __restrict__ x,
                       const float* __restrict__ WQ, const float* __restrict__ WK,
                       const float* __restrict__ WV, const int* __restrict__ e32) {
    int b = blockIdx.x;
    if (b < XH_BLOCKS) {
        int i = b * 256 + threadIdx.x;
        const float4* xp = (const float4*)(x + (size_t)i * 8);
        float4 v0 = xp[0], v1 = xp[1];
        __half hi[8];
        hi[0] = __float2half_rn(v0.x); hi[1] = __float2half_rn(v0.y);
        hi[2] = __float2half_rn(v0.z); hi[3] = __float2half_rn(v0.w);
        hi[4] = __float2half_rn(v1.x); hi[5] = __float2half_rn(v1.y);
        hi[6] = __float2half_rn(v1.z); hi[7] = __float2half_rn(v1.w);
        ((uint4*)g_xh)[i] = *(const uint4*)hi;
    } else if (b < XH_BLOCKS + ZERO_BLOCKS) {
        int j = (b - XH_BLOCKS) * 256 + threadIdx.x;
        if (j < NH) g_sum[j] = 0.0f;
    } else if (b < XH_BLOCKS + ZERO_BLOCKS + WC_BLOCKS) {
        int i = (b - XH_BLOCKS - ZERO_BLOCKS) * 256 + threadIdx.x;
        if (i < COLS * D_IN) {
            int m = i >> 7, d = i & 127;
            float w;
            if (m < 64)       w = WQ[d * 64 + m];
            else if (m < 128) w = WK[d * 64 + (m - 64)];
            else              w = WV[d * 64 + (m - 128)];
            g_wth[i] = __float2half_rn(w);
        }
    } else {
        // edge dtype detect: int64 edges (<1e5) have zero high words
        int any = 0;
        for (int i = threadIdx.x; i < 2048; i += 256)
            if (e32[2 * i + 1] != 0) any = 1;
        any = __syncthreads_or(any);
        if (threadIdx.x == 0) g_is64 = any ? 0 : 1;
    }
}

// ---------------- HMMA fp16 QKV projection (single term) ----------------
// Block: 128 rows x 48 cols, K=128. grid=(782,4). 256 threads = 8 warps
// (4M x 2N): warp tile 32x24 = 2x3 m16n8k16 tiles. 47KB smem -> 4 CTAs/SM.
// Epilogue stages results in smem, then writes coalesced streams.
#define PROJ_THREADS 256
#define RPB 128
#define NCB 48
#define KS 136
#define OS 56                          // staging row stride in floats (224B)

#define SM_XH 0
#define SM_WH (SM_XH + RPB * KS)
#define SM_END (SM_WH + NCB * KS)
#define PROJ_SMEM_BYTES (SM_END * 2 + NCB * 4)

#define MMA3(acc, ra0, ra1, ra2, ra3, rb0, rb1)                                  \
    asm volatile("mma.sync.aligned.m16n8k16.row.col.f32.f16.f16.f32 "            \
        "{%0,%1,%2,%3}, {%4,%5,%6,%7}, {%8,%9}, {%0,%1,%2,%3};"                  \
        : "+f"(acc[0]), "+f"(acc[1]), "+f"(acc[2]), "+f"(acc[3])                 \
        : "r"(ra0), "r"(ra1), "r"(ra2), "r"(ra3), "r"(rb0), "r"(rb1))

#define LDSM_X4(r0, r1, r2, r3, addr)                                            \
    asm volatile("ldmatrix.sync.aligned.m8n8.x4.shared.b16 {%0,%1,%2,%3}, [%4];" \
        : "=r"(r0), "=r"(r1), "=r"(r2), "=r"(r3) : "r"(addr))

#define LDSM_X2(r0, r1, addr)                                                    \
    asm volatile("ldmatrix.sync.aligned.m8n8.x2.shared.b16 {%0,%1}, [%2];"       \
        : "=r"(r0), "=r"(r1) : "r"(addr))

__global__ void __launch_bounds__(PROJ_THREADS, 4)
k_proj(const float* __restrict__ bQ, const float* __restrict__ bK,
       const float* __restrict__ bV, float* __restrict__ out_v) {
    extern __shared__ __half sm[];
    float* bsm = (float*)(sm + SM_END);
    float* sout = (float*)sm;          // reused after mainloop: [128][OS] floats

    const int tid = threadIdx.x;
    const int row0 = blockIdx.x * RPB;
    const int c0 = blockIdx.y * NCB;

    {
        const uint4* wh_g = (const uint4*)g_wth;
        for (int i = tid; i < NCB * D_IN / 8; i += PROJ_THREADS) {
            int m = i >> 4, c16 = i & 15;
            *(uint4*)(sm + SM_WH + m * KS + c16 * 8) = wh_g[(c0 + m) * 16 + c16];
        }
    }
    {
        const uint4* xh_g = (const uint4*)g_xh;
        const uint4 z = make_uint4(0, 0, 0, 0);
        for (int i = tid; i < RPB * D_IN / 8; i += PROJ_THREADS) {
            int r = i >> 4, c16 = i & 15;
            int row = row0 + r;
            uint4 v = (row < N_NODES) ? xh_g[row * 16 + c16] : z;
            *(uint4*)(sm + SM_XH + r * KS + c16 * 8) = v;
        }
    }
    for (int i = tid; i < NCB; i += PROJ_THREADS) {
        int m = c0 + i;
        bsm[i] = (m < 64) ? bQ[m] : (m < 128 ? bK[m - 64] : bV[m - 128]);
    }
    __syncthreads();

    const int lane = tid & 31;
    const int wid  = tid >> 5;
    const int wm   = wid & 3;
    const int wn   = wid >> 2;
    const int grp  = lane >> 2;
    const int tig  = lane & 3;

    float acc[2][3][4];
#pragma unroll
    for (int mi = 0; mi < 2; mi++)
#pragma unroll
        for (int ni = 0; ni < 3; ni++)
#pragma unroll
            for (int t = 0; t < 4; t++) acc[mi][ni][t] = 0.0f;

    const int a_half = SM_XH + (wm * 32 + (lane & 15)) * KS + ((lane & 16) ? 8 : 0);
    const int b_half = SM_WH + (wn * 24 + (lane & 7)) * KS + ((lane & 8) ? 8 : 0);
    const uint32_t a_base = (uint32_t)__cvta_generic_to_shared(sm + a_half);
    const uint32_t b_base = (uint32_t)__cvta_generic_to_shared(sm + b_half);

#pragma unroll
    for (int k0 = 0; k0 < 8; k0++) {
        const uint32_t kb = k0 * 32;
        uint32_t b[3][2];
#pragma unroll
        for (int ni = 0; ni < 3; ni++)
            LDSM_X2(b[ni][0], b[ni][1], b_base + ni * (8 * KS * 2) + kb);
        uint32_t a[2][4];
#pragma unroll
        for (int mi = 0; mi < 2; mi++)
            LDSM_X4(a[mi][0], a[mi][1], a[mi][2], a[mi][3],
                    a_base + mi * (16 * KS * 2) + kb);
#pragma unroll
        for (int mi = 0; mi < 2; mi++)
#pragma unroll
            for (int ni = 0; ni < 3; ni++)
                MMA3(acc[mi][ni], a[mi][0], a[mi][1], a[mi][2], a[mi][3],
                     b[ni][0], b[ni][1]);
    }

    // ---- stage biased results into smem (mainloop tiles dead now)
    __syncthreads();
#pragma unroll
    for (int mi = 0; mi < 2; mi++) {
#pragma unroll
        for (int ni = 0; ni < 3; ni++) {
            int lc = wn * 24 + ni * 8 + tig * 2;
            float b0 = bsm[lc], b1 = bsm[lc + 1];
#pragma unroll
            for (int half = 0; half < 2; half++) {
                int rl = wm * 32 + mi * 16 + grp + half * 8;
                float2 v;
                v.x = acc[mi][ni][half * 2 + 0] + b0;
                v.y = acc[mi][ni][half * 2 + 1] + b1;
                *(float2*)&sout[rl * OS + lc] = v;
            }
        }
    }
    __syncthreads();

    // ---- coalesced write-out by column slice
    const int by = blockIdx.y;
    if (by == 0) {
        // q cols 0..47
        for (int i = tid; i < RPB * 24; i += PROJ_THREADS) {
            int r = i / 24, jp = i % 24;
            int row = row0 + r;
            if (row < N_NODES) {
                float2 v = *(float2*)&sout[r * OS + jp * 2];
                *(__half2*)(g_qh + row * 64 + jp * 2) = __floats2half2_rn(v.x, v.y);
            }
        }
    } else if (by == 1) {
        // q cols 48..63 (jp 0..7), k cols 0..31 (jp 8..23)
        for (int i = tid; i < RPB * 24; i += PROJ_THREADS) {
            int r = i / 24, jp = i % 24;
            int row = row0 + r;
            if (row < N_NODES) {
                float2 v = *(float2*)&sout[r * OS + jp * 2];
                __half2 hv = __floats2half2_rn(v.x, v.y);
                if (jp < 8) *(__half2*)(g_qh + row * 64 + 48 + jp * 2) = hv;
                else        *(__half2*)(g_kh + row * 64 + (jp - 8) * 2) = hv;
            }
        }
    } else if (by == 2) {
        // k cols 32..63 (lc 0..31), v head-0 cc 0..15 (lc 32..47)
        for (int i = tid; i < RPB * 16; i += PROJ_THREADS) {
            int r = i / 16, jp = i % 16;
            int row = row0 + r;
            if (row < N_NODES) {
                float2 v = *(float2*)&sout[r * OS + jp * 2];
                *(__half2*)(g_kh + row * 64 + 32 + jp * 2) = __floats2half2_rn(v.x, v.y);
            }
        }
        for (int i = tid; i < RPB * 16; i += PROJ_THREADS) {
            int r = i / 16, dd = i % 16;
            int row = row0 + r;
            if (row < N_NODES)
                out_v[(size_t)row * 64 + dd * 4] = sout[r * OS + 32 + dd];
        }
    } else {
        // v cc 16..63 in output-offset order: j -> o=4g+m+1, lc=m*16+g
        for (int i = tid; i < RPB * 48; i += PROJ_THREADS) {
            int r = i / 48, j = i % 48;
            int row = row0 + r;
            if (row < N_NODES) {
                int g = j / 3, m = j - g * 3;
                out_v[(size_t)row * 64 + g * 4 + m + 1] = sout[r * OS + m * 16 + g];
            }
        }
    }
}

// ---------------- edge pass 1: prods + segment exp-sums (4 edges/thread) ----
__global__ void k_edge1(const void* __restrict__ edge_raw,
                        float* __restrict__ out_prods) {
    int t = blockIdx.x * blockDim.x + threadIdx.x;
    int p = t >> 3;
    if (p >= EQ) return;
    int sub = t & 7;

    int src[4], dst[4];
    if (g_is64) {
        const long long* ed = (const long long*)edge_raw;
#pragma unroll
        for (int i = 0; i < 4; i++) {
            src[i] = (int)ed[p + i * EQ];
            dst[i] = (int)ed[N_EDGES + p + i * EQ];
        }
    } else {
        const int* ed = (const int*)edge_raw;
#pragma unroll
        for (int i = 0; i < 4; i++) {
            src[i] = ed[p + i * EQ];
            dst[i] = ed[N_EDGES + p + i * EQ];
        }
    }

    uint4 qv[4], kv[4];
#pragma unroll
    for (int i = 0; i < 4; i++) {
        qv[i] = *(const uint4*)(g_qh + src[i] * 64 + sub * 8);
        kv[i] = *(const uint4*)(g_kh + dst[i] * 64 + sub * 8);
    }

    float dot[4];
#pragma unroll
    for (int i = 0; i < 4; i++) {
        const __half2* q = reinterpret_cast<const __half2*>(&qv[i]);
        const __half2* k = reinterpret_cast<const __half2*>(&kv[i]);
        __half2 a = __hmul2(q[0], k[0]);
        a = __hfma2(q[1], k[1], a);
        a = __hfma2(q[2], k[2], a);
        a = __hfma2(q[3], k[3], a);
        float d = __low2float(a) + __high2float(a);
        dot[i] = d + __shfl_xor_sync(0xffffffffu, d, 1);
    }

    if ((sub & 1) == 0) {
        int h = sub >> 1;
#pragma unroll
        for (int i = 0; i < 4; i++) {
            float pr = dot[i] * 0.25f;         // 1/sqrt(16)
            out_prods[(p + i * EQ) * 4 + h] = pr;
            atomicAdd(&g_sum[src[i] * 4 + h], __expf(pr));
        }
    }
}

// ---------------- edge pass 2: att = exp(prods)/sum[src] (4 edges/thread) ---
__global__ void k_edge2(const void* __restrict__ edge_raw,
                        const float* __restrict__ out_prods,
                        float* __restrict__ out_att) {
    int p = blockIdx.x * blockDim.x + threadIdx.x;
    if (p >= EQ) return;

    int src[4];
    if (g_is64) {
        const long long* ed = (const long long*)edge_raw;
#pragma unroll
        for (int i = 0; i < 4; i++) src[i] = (int)ed[p + i * EQ];
    } else {
        const int* ed = (const int*)edge_raw;
#pragma unroll
        for (int i = 0; i < 4; i++) src[i] = ed[p + i * EQ];
    }

    float4 pr[4], s[4];
#pragma unroll
    for (int i = 0; i < 4; i++) {
        pr[i] = reinterpret_cast<const float4*>(out_prods)[p + i * EQ];
        s[i]  = reinterpret_cast<const float4*>(g_sum)[src[i]];
    }
#pragma unroll
    for (int i = 0; i < 4; i++) {
        float4 r;
        r.x = __fdividef(__expf(pr[i].x), s[i].x + 1e-16f);
        r.y = __fdividef(__expf(pr[i].y), s[i].y + 1e-16f);
        r.z = __fdividef(__expf(pr[i].z), s[i].z + 1e-16f);
        r.w = __fdividef(__expf(pr[i].w), s[i].w + 1e-16f);
        reinterpret_cast<float4*>(out_att)[p + i * EQ] = r;
    }
}

// ---------------- launch ----------------
extern "C" void kernel_launch(void* const* d_in, const int* in_sizes, int n_in,
                              void* d_out, int out_size) {
    const float* x  = (const float*)d_in[0];
    const void*  edge = d_in[1];
    const float* WQ = (const float*)d_in[2];
    const float* bQ = (const float*)d_in[3];
    const float* WK = (const float*)d_in[4];
    const float* bK = (const float*)d_in[5];
    const float* WV = (const float*)d_in[6];
    const float* bV = (const float*)d_in[7];

    float* out       = (float*)d_out;
    float* out_att   = out;                                   // [E, 4]
    float* out_v     = out + (size_t)EH;                      // [N, 16, 4]
    float* out_prods = out_v + (size_t)N_NODES * ATT;         // [E, 4]

    cudaFuncSetAttribute(k_proj, cudaFuncAttributeMaxDynamicSharedMemorySize,
                         PROJ_SMEM_BYTES);

    k_prep<<<PREP_BLOCKS, 256>>>(x, WQ, WK, WV, (const int*)edge);

    dim3 pg((N_NODES + RPB - 1) / RPB, 4);                    // (782, 4)
    k_proj<<<pg, PROJ_THREADS, PROJ_SMEM_BYTES>>>(bQ, bK, bV, out_v);

    int nt1 = EQ * 8;
    k_edge1<<<(nt1 + 255) / 256, 256>>>(edge, out_prods);
    k_edge2<<<(EQ + 255) / 256, 256>>>(edge, out_prods, out_att);
}